// round 12
// baseline (speedup 1.0000x reference)
#include <cuda_runtime.h>
#include <cuda_bf16.h>
#include <math.h>
#include <stdint.h>

#define DIMC    768
#define HIDDENC 3072
#define SEQ     1024
#define BATCH   16
#define NTOK    (BATCH*SEQ)   // 16384
#define HEADSC  12
#define HDIM    64
#define QKVN    (3*DIMC)      // 2304
#define LN_EPS  1e-5f

typedef __nv_bfloat16 bf16;

// ---------------- scratch (static device arrays; no allocation allowed) ----------------
__device__ bf16  g_h_hi [NTOK*DIMC];
__device__ bf16  g_h_lo [NTOK*DIMC];
__device__ float g_qkv  [NTOK*QKVN];          // tf32-rounded fp32 (attention input)
__device__ bf16  g_ctx_hi[NTOK*DIMC];
__device__ bf16  g_ctx_lo[NTOK*DIMC];
__device__ float g_x1   [NTOK*DIMC];
__device__ bf16  g_h2_hi[NTOK*DIMC];
__device__ bf16  g_h2_lo[NTOK*DIMC];
__device__ bf16  g_ffn_hi[NTOK*HIDDENC];
__device__ bf16  g_ffn_lo[NTOK*HIDDENC];
// split TRANSPOSED weights, [N][K] row-major
__device__ bf16  g_wqkv_hi[QKVN*DIMC];
__device__ bf16  g_wqkv_lo[QKVN*DIMC];
__device__ float g_bqkv[QKVN];
__device__ bf16  g_wo_hi[DIMC*DIMC];
__device__ bf16  g_wo_lo[DIMC*DIMC];
__device__ bf16  g_w1_hi[HIDDENC*DIMC];
__device__ bf16  g_w1_lo[HIDDENC*DIMC];
__device__ bf16  g_w2_hi[DIMC*HIDDENC];
__device__ bf16  g_w2_lo[DIMC*HIDDENC];

// ---------------- helpers ----------------
__device__ __forceinline__ float tf32r(float x) {
    uint32_t u;
    asm("cvt.rna.tf32.f32 %0, %1;" : "=r"(u) : "f"(x));
    return __uint_as_float(u);
}

__device__ __forceinline__ void split_bf16(float v, bf16& hi, bf16& lo) {
    hi = __float2bfloat16_rn(v);
    lo = __float2bfloat16_rn(v - __bfloat162float(hi));
}

// tf32 m16n8k8 (attention)
__device__ __forceinline__ void mma_m16n8k8(float d[4], const uint32_t a[4], const uint32_t b[2]) {
    asm volatile(
        "mma.sync.aligned.m16n8k8.row.col.f32.tf32.tf32.f32 "
        "{%0,%1,%2,%3}, {%4,%5,%6,%7}, {%8,%9}, {%0,%1,%2,%3};"
        : "+f"(d[0]), "+f"(d[1]), "+f"(d[2]), "+f"(d[3])
        : "r"(a[0]), "r"(a[1]), "r"(a[2]), "r"(a[3]), "r"(b[0]), "r"(b[1]));
}

// bf16 m16n8k16 (GEMMs)
__device__ __forceinline__ void mma_bf16(float d[4], const uint32_t a[4], const uint32_t b[2]) {
    asm volatile(
        "mma.sync.aligned.m16n8k16.row.col.f32.bf16.bf16.f32 "
        "{%0,%1,%2,%3}, {%4,%5,%6,%7}, {%8,%9}, {%0,%1,%2,%3};"
        : "+f"(d[0]), "+f"(d[1]), "+f"(d[2]), "+f"(d[3])
        : "r"(a[0]), "r"(a[1]), "r"(a[2]), "r"(a[3]), "r"(b[0]), "r"(b[1]));
}

__device__ __forceinline__ void cp_async16(void* smem, const void* gmem) {
    uint32_t s = (uint32_t)__cvta_generic_to_shared(smem);
    asm volatile("cp.async.cg.shared.global [%0], [%1], 16;" :: "r"(s), "l"(gmem));
}

// ---------------- weight prep: tiled transpose fp32 [K][N] -> split bf16 [N][K] --------
__global__ __launch_bounds__(256) void transpose_split(
    const float* __restrict__ in, bf16* __restrict__ out_hi, bf16* __restrict__ out_lo,
    int K, int N)
{
    __shared__ float t[32][33];
    const int k0 = blockIdx.x * 32, n0 = blockIdx.y * 32;
    const int tx = threadIdx.x & 31, ty = threadIdx.x >> 5;   // 32x8
    #pragma unroll
    for (int i = 0; i < 32; i += 8)
        t[ty + i][tx] = in[(size_t)(k0 + ty + i) * N + n0 + tx];
    __syncthreads();
    #pragma unroll
    for (int i = 0; i < 32; i += 8) {
        bf16 hi, lo;
        split_bf16(t[tx][ty + i], hi, lo);
        out_hi[(size_t)(n0 + ty + i) * K + k0 + tx] = hi;
        out_lo[(size_t)(n0 + ty + i) * K + k0 + tx] = lo;
    }
}

__global__ void pack_qkv_b(const float* __restrict__ bq, const float* __restrict__ bk,
                           const float* __restrict__ bv, float* __restrict__ out)
{
    int j = blockIdx.x * 256 + threadIdx.x;
    if (j >= QKVN) return;
    out[j] = (j < DIMC) ? bq[j] : (j < 2 * DIMC) ? bk[j - DIMC] : bv[j - 2 * DIMC];
}

// ---------------- LayerNorm (split bf16 output) -----------------------------------------
__global__ __launch_bounds__(256) void ln_kernel(
    const float* __restrict__ x, const float* __restrict__ g,
    const float* __restrict__ b, bf16* __restrict__ ohi, bf16* __restrict__ olo)
{
    const int row = blockIdx.x;
    const int t = threadIdx.x;
    const float* xr = x + (size_t)row * DIMC;
    float v0 = xr[t], v1 = xr[t + 256], v2 = xr[t + 512];
    float s  = v0 + v1 + v2;
    float ss = v0*v0 + v1*v1 + v2*v2;
    #pragma unroll
    for (int o = 16; o; o >>= 1) {
        s  += __shfl_xor_sync(0xffffffffu, s,  o);
        ss += __shfl_xor_sync(0xffffffffu, ss, o);
    }
    __shared__ float sm[8], sm2[8];
    const int w = t >> 5, l = t & 31;
    if (l == 0) { sm[w] = s; sm2[w] = ss; }
    __syncthreads();
    if (w == 0) {
        s  = (l < 8) ? sm[l]  : 0.f;
        ss = (l < 8) ? sm2[l] : 0.f;
        #pragma unroll
        for (int o = 4; o; o >>= 1) {
            s  += __shfl_xor_sync(0xffffffffu, s,  o);
            ss += __shfl_xor_sync(0xffffffffu, ss, o);
        }
        if (l == 0) {
            float mu = s * (1.f / DIMC);
            sm[0]  = mu;
            sm2[0] = rsqrtf(ss * (1.f / DIMC) - mu * mu + LN_EPS);
        }
    }
    __syncthreads();
    const float mu = sm[0], rstd = sm2[0];
    #pragma unroll
    for (int i = 0; i < 3; i++) {
        const int c = t + i * 256;
        const float v = (i == 0 ? v0 : i == 1 ? v1 : v2);
        bf16 hi, lo;
        split_bf16((v - mu) * rstd * g[c] + b[c], hi, lo);
        ohi[(size_t)row * DIMC + c] = hi;
        olo[(size_t)row * DIMC + c] = lo;
    }
}

// ---------------- split-bf16 tensor-core GEMM ------------------------------------------
// C = act(A@Bt^T + bias) [+ res], A = Ahi+Alo [M,K], Bt = Bhi+Blo [N,K] (transposed W).
// D += Ahi*Bhi + Alo*Bhi + Ahi*Blo  (lo*lo dropped, <=2^-18).
// Block 128x128, 128 threads (4 warps 2x2, warp tile 64x64). K staged 32/iter, 2 stages.
// Pipeline order = R8 (proven): load-next -> wait 1 -> sync -> compute -> sync.
#define AS_STRIDE 40                  // halves: 32 k + 8 pad
#define TILE_H   (128*AS_STRIDE)      // halves per tile
#define GEMM_SMEM (2*4*TILE_H*2)      // 2 stages * 4 tiles * bytes = 81920

template<int OUTMODE>   // 0: fp32, 1: fp32 + tf32 round, 2: split bf16
__global__ __launch_bounds__(128) void gemm_split(
    const bf16* __restrict__ Ahi, const bf16* __restrict__ Alo,
    const bf16* __restrict__ Bhi, const bf16* __restrict__ Blo,
    const float* __restrict__ bias, const float* __restrict__ res,
    float* __restrict__ Cf, bf16* __restrict__ Chi, bf16* __restrict__ Clo,
    int M, int N, int K, int do_gelu)
{
    extern __shared__ bf16 smem[];

    const int bx = blockIdx.x * 128;
    const int by = blockIdx.y * 128;
    const int tid = threadIdx.x;
    const int wid = tid >> 5;
    const int lane = tid & 31;
    const int g  = lane >> 2;
    const int tg = lane & 3;

    const int wm = (wid & 1) * 64;
    const int wn = (wid >> 1) * 64;

    float acc[4][8][4];
    #pragma unroll
    for (int mt = 0; mt < 4; mt++)
        #pragma unroll
        for (int nt = 0; nt < 8; nt++)
            #pragma unroll
            for (int r = 0; r < 4; r++) acc[mt][nt][r] = 0.f;

    const int KT = K / 32;

    // stage layout: [stage][tile 0..3] = Ahi, Alo, Bhi, Blo
    auto load_stage = [&](int st, int k0) {
        bf16* base = smem + (size_t)st * 4 * TILE_H;
        #pragma unroll
        for (int i = 0; i < 4; i++) {
            const int idx = tid + 128 * i;        // 0..511
            const int row = idx >> 2;
            const int ch  = (idx & 3) * 8;        // halves
            const size_t aoff = (size_t)(by + row) * K + k0 + ch;
            const size_t boff = (size_t)(bx + row) * K + k0 + ch;
            cp_async16(&base[0 * TILE_H + row * AS_STRIDE + ch], Ahi + aoff);
            cp_async16(&base[1 * TILE_H + row * AS_STRIDE + ch], Alo + aoff);
            cp_async16(&base[2 * TILE_H + row * AS_STRIDE + ch], Bhi + boff);
            cp_async16(&base[3 * TILE_H + row * AS_STRIDE + ch], Blo + boff);
        }
        asm volatile("cp.async.commit_group;");
    };

    load_stage(0, 0);

    for (int kt = 0; kt < KT; kt++) {
        const int s = kt & 1;
        if (kt + 1 < KT) {
            load_stage(s ^ 1, (kt + 1) * 32);     // WAR safe: trailing sync of kt-1
            asm volatile("cp.async.wait_group 1;");
        } else {
            asm volatile("cp.async.wait_group 0;");
        }
        __syncthreads();

        const bf16* ahi = smem + (size_t)s * 4 * TILE_H;
        const bf16* alo = ahi + TILE_H;
        const bf16* bhi = ahi + 2 * TILE_H;
        const bf16* blo = ahi + 3 * TILE_H;

        #pragma unroll
        for (int kk = 0; kk < 32; kk += 16) {
            uint32_t afh[4][4], afl[4][4];
            #pragma unroll
            for (int mt = 0; mt < 4; mt++) {
                const int m0 = wm + mt * 16 + g;
                const int o00 = m0 * AS_STRIDE + kk + 2 * tg;
                const int o10 = (m0 + 8) * AS_STRIDE + kk + 2 * tg;
                afh[mt][0] = *(const uint32_t*)&ahi[o00];
                afh[mt][1] = *(const uint32_t*)&ahi[o10];
                afh[mt][2] = *(const uint32_t*)&ahi[o00 + 8];
                afh[mt][3] = *(const uint32_t*)&ahi[o10 + 8];
                afl[mt][0] = *(const uint32_t*)&alo[o00];
                afl[mt][1] = *(const uint32_t*)&alo[o10];
                afl[mt][2] = *(const uint32_t*)&alo[o00 + 8];
                afl[mt][3] = *(const uint32_t*)&alo[o10 + 8];
            }
            uint32_t bfh[8][2], bfl[8][2];
            #pragma unroll
            for (int nt = 0; nt < 8; nt++) {
                const int n0 = (wn + nt * 8 + g) * AS_STRIDE + kk + 2 * tg;
                bfh[nt][0] = *(const uint32_t*)&bhi[n0];
                bfh[nt][1] = *(const uint32_t*)&bhi[n0 + 8];
                bfl[nt][0] = *(const uint32_t*)&blo[n0];
                bfl[nt][1] = *(const uint32_t*)&blo[n0 + 8];
            }
            #pragma unroll
            for (int mt = 0; mt < 4; mt++)
                #pragma unroll
                for (int nt = 0; nt < 8; nt++) {
                    mma_bf16(acc[mt][nt], afh[mt], bfh[nt]);
                    mma_bf16(acc[mt][nt], afl[mt], bfh[nt]);
                    mma_bf16(acc[mt][nt], afh[mt], bfl[nt]);
                }
        }
        __syncthreads();
    }

    // epilogue: bias (+gelu) (+fp32 residual) -> fp32 / tf32-rounded fp32 / split bf16
    #pragma unroll
    for (int mt = 0; mt < 4; mt++) {
        const int r0 = by + wm + mt * 16 + g;
        #pragma unroll
        for (int nt = 0; nt < 8; nt++) {
            const int c0 = bx + wn + nt * 8 + tg * 2;
            const float b0 = bias[c0], b1 = bias[c0 + 1];
            float v[4];
            v[0] = acc[mt][nt][0] + b0;
            v[1] = acc[mt][nt][1] + b1;
            v[2] = acc[mt][nt][2] + b0;
            v[3] = acc[mt][nt][3] + b1;
            if (do_gelu) {
                #pragma unroll
                for (int u = 0; u < 4; u++)
                    v[u] = 0.5f * v[u] * (1.0f + erff(v[u] * 0.70710678118654752f));
            }
            if (res) {
                const float2 r01 = *(const float2*)&res[(size_t)r0 * N + c0];
                const float2 r11 = *(const float2*)&res[(size_t)(r0 + 8) * N + c0];
                v[0] += r01.x; v[1] += r01.y;
                v[2] += r11.x; v[3] += r11.y;
            }
            if (OUTMODE == 2) {
                bf16 h0, l0, h1, l1;
                split_bf16(v[0], h0, l0); split_bf16(v[1], h1, l1);
                *(__nv_bfloat162*)&Chi[(size_t)r0 * N + c0] = __nv_bfloat162(h0, h1);
                *(__nv_bfloat162*)&Clo[(size_t)r0 * N + c0] = __nv_bfloat162(l0, l1);
                split_bf16(v[2], h0, l0); split_bf16(v[3], h1, l1);
                *(__nv_bfloat162*)&Chi[(size_t)(r0 + 8) * N + c0] = __nv_bfloat162(h0, h1);
                *(__nv_bfloat162*)&Clo[(size_t)(r0 + 8) * N + c0] = __nv_bfloat162(l0, l1);
            } else {
                if (OUTMODE == 1) {
                    #pragma unroll
                    for (int u = 0; u < 4; u++) v[u] = tf32r(v[u]);
                }
                *(float2*)&Cf[(size_t)r0 * N + c0]       = make_float2(v[0], v[1]);
                *(float2*)&Cf[(size_t)(r0 + 8) * N + c0] = make_float2(v[2], v[3]);
            }
        }
    }
}

// ---------------- TF32 flash attention (R8 proven version; ctx -> split bf16) ----------
#define KS_STRIDE 68
#define VS_STRIDE 72

__global__ __launch_bounds__(128) void attn_tc(
    const float* __restrict__ qkv, bf16* __restrict__ ctx_hi, bf16* __restrict__ ctx_lo)
{
    const int qt = blockIdx.x, h = blockIdx.y, b = blockIdx.z;
    const int tid = threadIdx.x, w = tid >> 5, lane = tid & 31;
    const int g = lane >> 2, tg = lane & 3;

    __shared__ float Ks[64][KS_STRIDE];   // K tile, then per-m-tile P staging
    __shared__ float Vs[64][VS_STRIDE];

    const int qrow0 = b * SEQ + qt * 128 + w * 32;
    const float* qbase = qkv + (size_t)qrow0 * QKVN + h * HDIM;

    uint32_t af[2][8][4];
    #pragma unroll
    for (int mt = 0; mt < 2; mt++)
        #pragma unroll
        for (int c = 0; c < 8; c++) {
            const int r0 = mt * 16 + g;
            af[mt][c][0] = __float_as_uint(0.125f * qbase[(size_t)r0       * QKVN + c * 8 + tg]);
            af[mt][c][1] = __float_as_uint(0.125f * qbase[(size_t)(r0 + 8) * QKVN + c * 8 + tg]);
            af[mt][c][2] = __float_as_uint(0.125f * qbase[(size_t)r0       * QKVN + c * 8 + tg + 4]);
            af[mt][c][3] = __float_as_uint(0.125f * qbase[(size_t)(r0 + 8) * QKVN + c * 8 + tg + 4]);
        }

    float o[2][8][4];
    #pragma unroll
    for (int mt = 0; mt < 2; mt++)
        #pragma unroll
        for (int nt = 0; nt < 8; nt++)
            #pragma unroll
            for (int r = 0; r < 4; r++) o[mt][nt][r] = 0.f;
    float mst[2][2] = {{-1e30f, -1e30f}, {-1e30f, -1e30f}};
    float lst[2][2] = {{0.f, 0.f}, {0.f, 0.f}};

    for (int kt = 0; kt < SEQ / 64; kt++) {
        const float* kb = qkv + (size_t)(b * SEQ + kt * 64) * QKVN + DIMC + h * HDIM;
        const float* vb = kb + DIMC;
        #pragma unroll
        for (int it = 0; it < 8; it++) {
            int e4  = it * 128 + tid;
            int row = e4 >> 4;
            int d4  = (e4 & 15) * 4;
            *(float4*)&Ks[row][d4] = *(const float4*)(kb + (size_t)row * QKVN + d4);
            *(float4*)&Vs[row][d4] = *(const float4*)(vb + (size_t)row * QKVN + d4);
        }
        __syncthreads();

        float sc[2][8][4];
        #pragma unroll
        for (int mt = 0; mt < 2; mt++)
            #pragma unroll
            for (int nt = 0; nt < 8; nt++)
                #pragma unroll
                for (int r = 0; r < 4; r++) sc[mt][nt][r] = 0.f;
        #pragma unroll
        for (int c = 0; c < 8; c++) {
            #pragma unroll
            for (int nt = 0; nt < 8; nt++) {
                uint32_t bf[2];
                bf[0] = __float_as_uint(Ks[nt * 8 + g][c * 8 + tg]);
                bf[1] = __float_as_uint(Ks[nt * 8 + g][c * 8 + tg + 4]);
                mma_m16n8k8(sc[0][nt], af[0][c], bf);
                mma_m16n8k8(sc[1][nt], af[1][c], bf);
            }
        }

        float alpha[2][2];
        #pragma unroll
        for (int mt = 0; mt < 2; mt++) {
            float tm0 = -1e30f, tm1 = -1e30f;
            #pragma unroll
            for (int nt = 0; nt < 8; nt++) {
                tm0 = fmaxf(tm0, fmaxf(sc[mt][nt][0], sc[mt][nt][1]));
                tm1 = fmaxf(tm1, fmaxf(sc[mt][nt][2], sc[mt][nt][3]));
            }
            tm0 = fmaxf(tm0, __shfl_xor_sync(0xffffffffu, tm0, 1));
            tm0 = fmaxf(tm0, __shfl_xor_sync(0xffffffffu, tm0, 2));
            tm1 = fmaxf(tm1, __shfl_xor_sync(0xffffffffu, tm1, 1));
            tm1 = fmaxf(tm1, __shfl_xor_sync(0xffffffffu, tm1, 2));
            const float mn0 = fmaxf(mst[mt][0], tm0), mn1 = fmaxf(mst[mt][1], tm1);
            alpha[mt][0] = __expf(mst[mt][0] - mn0);
            alpha[mt][1] = __expf(mst[mt][1] - mn1);
            mst[mt][0] = mn0; mst[mt][1] = mn1;

            float rs0 = 0.f, rs1 = 0.f;
            #pragma unroll
            for (int nt = 0; nt < 8; nt++) {
                sc[mt][nt][0] = __expf(sc[mt][nt][0] - mn0);
                sc[mt][nt][1] = __expf(sc[mt][nt][1] - mn0);
                sc[mt][nt][2] = __expf(sc[mt][nt][2] - mn1);
                sc[mt][nt][3] = __expf(sc[mt][nt][3] - mn1);
                rs0 += sc[mt][nt][0] + sc[mt][nt][1];
                rs1 += sc[mt][nt][2] + sc[mt][nt][3];
            }
            rs0 += __shfl_xor_sync(0xffffffffu, rs0, 1);
            rs0 += __shfl_xor_sync(0xffffffffu, rs0, 2);
            rs1 += __shfl_xor_sync(0xffffffffu, rs1, 1);
            rs1 += __shfl_xor_sync(0xffffffffu, rs1, 2);
            lst[mt][0] = lst[mt][0] * alpha[mt][0] + rs0;
            lst[mt][1] = lst[mt][1] * alpha[mt][1] + rs1;

            #pragma unroll
            for (int nt = 0; nt < 8; nt++) {
                o[mt][nt][0] *= alpha[mt][0]; o[mt][nt][1] *= alpha[mt][0];
                o[mt][nt][2] *= alpha[mt][1]; o[mt][nt][3] *= alpha[mt][1];
            }
        }

        __syncthreads();   // all warps done reading K tile before P overwrites it

        #pragma unroll
        for (int mt = 0; mt < 2; mt++) {
            #pragma unroll
            for (int nt = 0; nt < 8; nt++) {
                *(float2*)&Ks[w * 16 + g][nt * 8 + 2 * tg]     = make_float2(tf32r(sc[mt][nt][0]), tf32r(sc[mt][nt][1]));
                *(float2*)&Ks[w * 16 + g + 8][nt * 8 + 2 * tg] = make_float2(tf32r(sc[mt][nt][2]), tf32r(sc[mt][nt][3]));
            }
            __syncwarp();

            #pragma unroll
            for (int c = 0; c < 8; c++) {
                uint32_t pa[4];
                pa[0] = __float_as_uint(Ks[w * 16 + g][c * 8 + tg]);
                pa[1] = __float_as_uint(Ks[w * 16 + g + 8][c * 8 + tg]);
                pa[2] = __float_as_uint(Ks[w * 16 + g][c * 8 + tg + 4]);
                pa[3] = __float_as_uint(Ks[w * 16 + g + 8][c * 8 + tg + 4]);
                #pragma unroll
                for (int nt = 0; nt < 8; nt++) {
                    uint32_t vbf[2];
                    vbf[0] = __float_as_uint(Vs[c * 8 + tg][nt * 8 + g]);
                    vbf[1] = __float_as_uint(Vs[c * 8 + tg + 4][nt * 8 + g]);
                    mma_m16n8k8(o[mt][nt], pa, vbf);
                }
            }
            __syncwarp();
        }
        __syncthreads();
    }

    #pragma unroll
    for (int mt = 0; mt < 2; mt++) {
        const float inv0 = 1.f / lst[mt][0], inv1 = 1.f / lst[mt][1];
        const size_t r0 = (size_t)(qrow0 + mt * 16 + g)     * DIMC + h * HDIM;
        const size_t r1 = (size_t)(qrow0 + mt * 16 + g + 8) * DIMC + h * HDIM;
        #pragma unroll
        for (int nt = 0; nt < 8; nt++) {
            bf16 h0, l0, h1, l1;
            split_bf16(o[mt][nt][0] * inv0, h0, l0);
            split_bf16(o[mt][nt][1] * inv0, h1, l1);
            *(__nv_bfloat162*)&ctx_hi[r0 + nt * 8 + 2 * tg] = __nv_bfloat162(h0, h1);
            *(__nv_bfloat162*)&ctx_lo[r0 + nt * 8 + 2 * tg] = __nv_bfloat162(l0, l1);
            split_bf16(o[mt][nt][2] * inv1, h0, l0);
            split_bf16(o[mt][nt][3] * inv1, h1, l1);
            *(__nv_bfloat162*)&ctx_hi[r1 + nt * 8 + 2 * tg] = __nv_bfloat162(h0, h1);
            *(__nv_bfloat162*)&ctx_lo[r1 + nt * 8 + 2 * tg] = __nv_bfloat162(l0, l1);
        }
    }
}

// ---------------- launch ----------------
extern "C" void kernel_launch(void* const* d_in, const int* in_sizes, int n_in,
                              void* d_out, int out_size)
{
    const float* x    = (const float*)d_in[0];
    const float* ln1g = (const float*)d_in[1];
    const float* ln1b = (const float*)d_in[2];
    const float* Wq   = (const float*)d_in[3];
    const float* bq   = (const float*)d_in[4];
    const float* Wk   = (const float*)d_in[5];
    const float* bk   = (const float*)d_in[6];
    const float* Wv   = (const float*)d_in[7];
    const float* bv   = (const float*)d_in[8];
    const float* Wo   = (const float*)d_in[9];
    const float* bo   = (const float*)d_in[10];
    const float* ln2g = (const float*)d_in[11];
    const float* ln2b = (const float*)d_in[12];
    const float* W1   = (const float*)d_in[13];
    const float* b1   = (const float*)d_in[14];
    const float* W2   = (const float*)d_in[15];
    const float* b2   = (const float*)d_in[16];
    float* out = (float*)d_out;

    bf16 *hhi, *hlo, *ctxhi, *ctxlo, *h2hi, *h2lo, *ffnhi, *ffnlo;
    bf16 *wqkvhi, *wqkvlo, *wohi, *wolo, *w1hi, *w1lo, *w2hi, *w2lo;
    float *qkv, *x1, *bqkv;
    cudaGetSymbolAddress((void**)&hhi,    g_h_hi);
    cudaGetSymbolAddress((void**)&hlo,    g_h_lo);
    cudaGetSymbolAddress((void**)&qkv,    g_qkv);
    cudaGetSymbolAddress((void**)&ctxhi,  g_ctx_hi);
    cudaGetSymbolAddress((void**)&ctxlo,  g_ctx_lo);
    cudaGetSymbolAddress((void**)&x1,     g_x1);
    cudaGetSymbolAddress((void**)&h2hi,   g_h2_hi);
    cudaGetSymbolAddress((void**)&h2lo,   g_h2_lo);
    cudaGetSymbolAddress((void**)&ffnhi,  g_ffn_hi);
    cudaGetSymbolAddress((void**)&ffnlo,  g_ffn_lo);
    cudaGetSymbolAddress((void**)&wqkvhi, g_wqkv_hi);
    cudaGetSymbolAddress((void**)&wqkvlo, g_wqkv_lo);
    cudaGetSymbolAddress((void**)&bqkv,   g_bqkv);
    cudaGetSymbolAddress((void**)&wohi,   g_wo_hi);
    cudaGetSymbolAddress((void**)&wolo,   g_wo_lo);
    cudaGetSymbolAddress((void**)&w1hi,   g_w1_hi);
    cudaGetSymbolAddress((void**)&w1lo,   g_w1_lo);
    cudaGetSymbolAddress((void**)&w2hi,   g_w2_hi);
    cudaGetSymbolAddress((void**)&w2lo,   g_w2_lo);

    cudaFuncSetAttribute(gemm_split<0>, cudaFuncAttributeMaxDynamicSharedMemorySize, GEMM_SMEM);
    cudaFuncSetAttribute(gemm_split<1>, cudaFuncAttributeMaxDynamicSharedMemorySize, GEMM_SMEM);
    cudaFuncSetAttribute(gemm_split<2>, cudaFuncAttributeMaxDynamicSharedMemorySize, GEMM_SMEM);

    const dim3 blk(256);
    const dim3 gblk(128);

    // weight prep: transpose fp32 -> split bf16 [N][K]
    transpose_split<<<dim3(DIMC/32, DIMC/32), 256>>>(Wq, wqkvhi,                 wqkvlo,                 DIMC, DIMC);
    transpose_split<<<dim3(DIMC/32, DIMC/32), 256>>>(Wk, wqkvhi + DIMC*DIMC,     wqkvlo + DIMC*DIMC,     DIMC, DIMC);
    transpose_split<<<dim3(DIMC/32, DIMC/32), 256>>>(Wv, wqkvhi + 2*DIMC*DIMC,   wqkvlo + 2*DIMC*DIMC,   DIMC, DIMC);
    pack_qkv_b<<<(QKVN + 255) / 256, blk>>>(bq, bk, bv, bqkv);
    transpose_split<<<dim3(DIMC/32, DIMC/32),    256>>>(Wo, wohi, wolo, DIMC, DIMC);
    transpose_split<<<dim3(DIMC/32, HIDDENC/32), 256>>>(W1, w1hi, w1lo, DIMC, HIDDENC);
    transpose_split<<<dim3(HIDDENC/32, DIMC/32), 256>>>(W2, w2hi, w2lo, HIDDENC, DIMC);

    const dim3 gqkv(QKVN / 128, NTOK / 128);     // 18 x 128
    const dim3 gd(DIMC / 128, NTOK / 128);       // 6 x 128
    const dim3 gh(HIDDENC / 128, NTOK / 128);    // 24 x 128

    // 1) LN1 -> split bf16
    ln_kernel<<<NTOK, blk>>>(x, ln1g, ln1b, hhi, hlo);
    // 2) fused QKV projection -> fp32 qkv (tf32-rounded for attention)
    gemm_split<1><<<gqkv, gblk, GEMM_SMEM>>>(hhi, hlo, wqkvhi, wqkvlo, bqkv, nullptr,
                                             qkv, nullptr, nullptr, NTOK, QKVN, DIMC, 0);
    // 3) flash attention (tf32) -> split bf16 ctx
    attn_tc<<<dim3(SEQ / 128, HEADSC, BATCH), 128>>>(qkv, ctxhi, ctxlo);
    // 4) x1 = x + ctx@Wo + bo (fp32 out)
    gemm_split<0><<<gd, gblk, GEMM_SMEM>>>(ctxhi, ctxlo, wohi, wolo, bo, x,
                                           x1, nullptr, nullptr, NTOK, DIMC, DIMC, 0);
    // 5) LN2 -> split bf16
    ln_kernel<<<NTOK, blk>>>(x1, ln2g, ln2b, h2hi, h2lo);
    // 6) FFN up + exact GELU -> split bf16
    gemm_split<2><<<gh, gblk, GEMM_SMEM>>>(h2hi, h2lo, w1hi, w1lo, b1, nullptr,
                                           nullptr, ffnhi, ffnlo, NTOK, HIDDENC, DIMC, 1);
    // 7) out = x1 + ffn@W2 + b2 (fp32 out)
    gemm_split<0><<<gd, gblk, GEMM_SMEM>>>(ffnhi, ffnlo, w2hi, w2lo, b2, x1,
                                           out, nullptr, nullptr, NTOK, DIMC, HIDDENC, 0);
}

// round 13
// speedup vs baseline: 1.9609x; 1.9609x over previous
#include <cuda_runtime.h>
#include <cuda_fp16.h>
#include <math.h>
#include <stdint.h>

#define DIMC    768
#define HIDDENC 3072
#define SEQ     1024
#define BATCH   16
#define NTOK    (BATCH*SEQ)   // 16384
#define HEADSC  12
#define HDIM    64
#define QKVN    (3*DIMC)      // 2304
#define LN_EPS  1e-5f

// ---------------- scratch (static device arrays; no allocation allowed) ----------------
__device__ __half g_h   [NTOK*DIMC];
__device__ float  g_qkv [NTOK*QKVN];     // tf32-rounded fp32 (attention input)
__device__ __half g_ctx [NTOK*DIMC];
__device__ float  g_x1  [NTOK*DIMC];
__device__ __half g_h2  [NTOK*DIMC];
__device__ __half g_ffn [NTOK*HIDDENC];
// fp16 TRANSPOSED weights, [N][K] row-major
__device__ __half g_wqkv[QKVN*DIMC];
__device__ float  g_bqkv[QKVN];
__device__ __half g_wo  [DIMC*DIMC];
__device__ __half g_w1  [HIDDENC*DIMC];
__device__ __half g_w2  [DIMC*HIDDENC];

// ---------------- helpers ----------------
__device__ __forceinline__ float tf32r(float x) {
    uint32_t u;
    asm("cvt.rna.tf32.f32 %0, %1;" : "=r"(u) : "f"(x));
    return __uint_as_float(u);
}

// tf32 m16n8k8 (attention)
__device__ __forceinline__ void mma_m16n8k8(float d[4], const uint32_t a[4], const uint32_t b[2]) {
    asm volatile(
        "mma.sync.aligned.m16n8k8.row.col.f32.tf32.tf32.f32 "
        "{%0,%1,%2,%3}, {%4,%5,%6,%7}, {%8,%9}, {%0,%1,%2,%3};"
        : "+f"(d[0]), "+f"(d[1]), "+f"(d[2]), "+f"(d[3])
        : "r"(a[0]), "r"(a[1]), "r"(a[2]), "r"(a[3]), "r"(b[0]), "r"(b[1]));
}

// fp16 m16n8k16 (GEMMs), fp32 accumulate
__device__ __forceinline__ void mma_f16(float d[4], const uint32_t a[4], const uint32_t b[2]) {
    asm volatile(
        "mma.sync.aligned.m16n8k16.row.col.f32.f16.f16.f32 "
        "{%0,%1,%2,%3}, {%4,%5,%6,%7}, {%8,%9}, {%0,%1,%2,%3};"
        : "+f"(d[0]), "+f"(d[1]), "+f"(d[2]), "+f"(d[3])
        : "r"(a[0]), "r"(a[1]), "r"(a[2]), "r"(a[3]), "r"(b[0]), "r"(b[1]));
}

__device__ __forceinline__ void cp_async16(void* smem, const void* gmem) {
    uint32_t s = (uint32_t)__cvta_generic_to_shared(smem);
    asm volatile("cp.async.cg.shared.global [%0], [%1], 16;" :: "r"(s), "l"(gmem));
}

// epilogue stores (overloaded on output type)
__device__ __forceinline__ void store2(float* p, float a, float b, int rnd) {
    if (rnd) { a = tf32r(a); b = tf32r(b); }
    *(float2*)p = make_float2(a, b);
}
__device__ __forceinline__ void store2(__half* p, float a, float b, int) {
    *(__half2*)p = __floats2half2_rn(a, b);
}

// ---------------- weight prep: tiled transpose fp32 [K][N] -> fp16 [N][K] --------------
__global__ __launch_bounds__(256) void transpose_f16(
    const float* __restrict__ in, __half* __restrict__ out, int K, int N)
{
    __shared__ float t[32][33];
    const int k0 = blockIdx.x * 32, n0 = blockIdx.y * 32;
    const int tx = threadIdx.x & 31, ty = threadIdx.x >> 5;   // 32x8
    #pragma unroll
    for (int i = 0; i < 32; i += 8)
        t[ty + i][tx] = in[(size_t)(k0 + ty + i) * N + n0 + tx];
    __syncthreads();
    #pragma unroll
    for (int i = 0; i < 32; i += 8)
        out[(size_t)(n0 + ty + i) * K + k0 + tx] = __float2half_rn(t[tx][ty + i]);
}

__global__ void pack_qkv_b(const float* __restrict__ bq, const float* __restrict__ bk,
                           const float* __restrict__ bv, float* __restrict__ out)
{
    int j = blockIdx.x * 256 + threadIdx.x;
    if (j >= QKVN) return;
    out[j] = (j < DIMC) ? bq[j] : (j < 2 * DIMC) ? bk[j - DIMC] : bv[j - 2 * DIMC];
}

// ---------------- LayerNorm (fp16 output; feeds GEMM A) --------------------------------
__global__ __launch_bounds__(256) void ln_kernel(
    const float* __restrict__ x, const float* __restrict__ g,
    const float* __restrict__ b, __half* __restrict__ out)
{
    const int row = blockIdx.x;
    const int t = threadIdx.x;
    const float* xr = x + (size_t)row * DIMC;
    float v0 = xr[t], v1 = xr[t + 256], v2 = xr[t + 512];
    float s  = v0 + v1 + v2;
    float ss = v0*v0 + v1*v1 + v2*v2;
    #pragma unroll
    for (int o = 16; o; o >>= 1) {
        s  += __shfl_xor_sync(0xffffffffu, s,  o);
        ss += __shfl_xor_sync(0xffffffffu, ss, o);
    }
    __shared__ float sm[8], sm2[8];
    const int w = t >> 5, l = t & 31;
    if (l == 0) { sm[w] = s; sm2[w] = ss; }
    __syncthreads();
    if (w == 0) {
        s  = (l < 8) ? sm[l]  : 0.f;
        ss = (l < 8) ? sm2[l] : 0.f;
        #pragma unroll
        for (int o = 4; o; o >>= 1) {
            s  += __shfl_xor_sync(0xffffffffu, s,  o);
            ss += __shfl_xor_sync(0xffffffffu, ss, o);
        }
        if (l == 0) {
            float mu = s * (1.f / DIMC);
            sm[0]  = mu;
            sm2[0] = rsqrtf(ss * (1.f / DIMC) - mu * mu + LN_EPS);
        }
    }
    __syncthreads();
    const float mu = sm[0], rstd = sm2[0];
    __half* orow = out + (size_t)row * DIMC;
    orow[t]       = __float2half_rn((v0 - mu) * rstd * g[t]       + b[t]);
    orow[t + 256] = __float2half_rn((v1 - mu) * rstd * g[t + 256] + b[t + 256]);
    orow[t + 512] = __float2half_rn((v2 - mu) * rstd * g[t + 512] + b[t + 512]);
}

// ---------------- FP16 tensor-core GEMM: C = act(A@Bt^T + bias) [+ res] ----------------
// A: [M,K] fp16 row-major. Bt: [N,K] fp16 row-major (transposed weight).
// Block 128x128, 128 threads (4 warps 2x2, warp tile 64x64), K staged 32/iter,
// double-buffered (R8 proven order: load-next -> wait 1 -> sync -> compute -> sync).
#define AS_STRIDE 40                 // halves: 32 k + 8 pad; banks (20g+tg) mod 32 bijective
#define A_TILE (128*AS_STRIDE)       // halves

template<typename OutT>
__global__ __launch_bounds__(128) void gemm_f16(
    const __half* __restrict__ A, const __half* __restrict__ Bt,
    const float* __restrict__ bias, const float* __restrict__ res,
    OutT* __restrict__ C, int M, int N, int K, int do_gelu, int rnd)
{
    __shared__ alignas(16) __half As[2][A_TILE];
    __shared__ alignas(16) __half Bs[2][A_TILE];

    const int bx = blockIdx.x * 128;
    const int by = blockIdx.y * 128;
    const int tid = threadIdx.x;
    const int wid = tid >> 5;
    const int lane = tid & 31;
    const int g  = lane >> 2;
    const int tg = lane & 3;

    const int wm = (wid & 1) * 64;
    const int wn = (wid >> 1) * 64;

    float acc[4][8][4];
    #pragma unroll
    for (int mt = 0; mt < 4; mt++)
        #pragma unroll
        for (int nt = 0; nt < 8; nt++)
            #pragma unroll
            for (int r = 0; r < 4; r++) acc[mt][nt][r] = 0.f;

    const int KT = K / 32;

    // producer: per stage, A and Bt are 128 rows x 32 halves = 64B/row = 4 chunks each
    auto load_stage = [&](int st, int k0) {
        #pragma unroll
        for (int i = 0; i < 4; i++) {
            const int idx = tid + 128 * i;        // 0..511
            const int row = idx >> 2;
            const int ch  = (idx & 3) * 8;        // halves offset
            cp_async16(&As[st][row * AS_STRIDE + ch], A  + (size_t)(by + row) * K + k0 + ch);
            cp_async16(&Bs[st][row * AS_STRIDE + ch], Bt + (size_t)(bx + row) * K + k0 + ch);
        }
        asm volatile("cp.async.commit_group;");
    };

    load_stage(0, 0);

    for (int kt = 0; kt < KT; kt++) {
        const int s = kt & 1;
        if (kt + 1 < KT) {
            load_stage(s ^ 1, (kt + 1) * 32);     // WAR safe: trailing sync of kt-1
            asm volatile("cp.async.wait_group 1;");
        } else {
            asm volatile("cp.async.wait_group 0;");
        }
        __syncthreads();

        const __half* as = As[s];
        const __half* bs = Bs[s];
        #pragma unroll
        for (int kk = 0; kk < 32; kk += 16) {
            uint32_t af[4][4];
            #pragma unroll
            for (int mt = 0; mt < 4; mt++) {
                const int m0 = wm + mt * 16 + g;
                af[mt][0] = *(const uint32_t*)&as[m0 * AS_STRIDE + kk + 2 * tg];
                af[mt][1] = *(const uint32_t*)&as[(m0 + 8) * AS_STRIDE + kk + 2 * tg];
                af[mt][2] = *(const uint32_t*)&as[m0 * AS_STRIDE + kk + 2 * tg + 8];
                af[mt][3] = *(const uint32_t*)&as[(m0 + 8) * AS_STRIDE + kk + 2 * tg + 8];
            }
            uint32_t bf[8][2];
            #pragma unroll
            for (int nt = 0; nt < 8; nt++) {
                const int n0 = wn + nt * 8 + g;
                bf[nt][0] = *(const uint32_t*)&bs[n0 * AS_STRIDE + kk + 2 * tg];
                bf[nt][1] = *(const uint32_t*)&bs[n0 * AS_STRIDE + kk + 2 * tg + 8];
            }
            #pragma unroll
            for (int mt = 0; mt < 4; mt++)
                #pragma unroll
                for (int nt = 0; nt < 8; nt++)
                    mma_f16(acc[mt][nt], af[mt], bf[nt]);
        }
        __syncthreads();
    }

    // epilogue: bias (+gelu) (+fp32 residual) -> OutT
    #pragma unroll
    for (int mt = 0; mt < 4; mt++) {
        const int r0 = by + wm + mt * 16 + g;
        #pragma unroll
        for (int nt = 0; nt < 8; nt++) {
            const int c0 = bx + wn + nt * 8 + tg * 2;
            const float b0 = bias[c0], b1 = bias[c0 + 1];
            float v00 = acc[mt][nt][0] + b0;
            float v01 = acc[mt][nt][1] + b1;
            float v10 = acc[mt][nt][2] + b0;
            float v11 = acc[mt][nt][3] + b1;
            if (do_gelu) {
                v00 = 0.5f * v00 * (1.0f + erff(v00 * 0.70710678118654752f));
                v01 = 0.5f * v01 * (1.0f + erff(v01 * 0.70710678118654752f));
                v10 = 0.5f * v10 * (1.0f + erff(v10 * 0.70710678118654752f));
                v11 = 0.5f * v11 * (1.0f + erff(v11 * 0.70710678118654752f));
            }
            if (res) {
                const float2 r01 = *(const float2*)&res[(size_t)r0 * N + c0];
                const float2 r11 = *(const float2*)&res[(size_t)(r0 + 8) * N + c0];
                v00 += r01.x; v01 += r01.y;
                v10 += r11.x; v11 += r11.y;
            }
            store2(&C[(size_t)r0 * N + c0],       v00, v01, rnd);
            store2(&C[(size_t)(r0 + 8) * N + c0], v10, v11, rnd);
        }
    }
}

// ---------------- TF32 flash attention (R8 proven version; ctx -> fp16) ----------------
#define KS_STRIDE 68
#define VS_STRIDE 72

__global__ __launch_bounds__(128) void attn_tc(
    const float* __restrict__ qkv, __half* __restrict__ ctx)
{
    const int qt = blockIdx.x, h = blockIdx.y, b = blockIdx.z;
    const int tid = threadIdx.x, w = tid >> 5, lane = tid & 31;
    const int g = lane >> 2, tg = lane & 3;

    __shared__ float Ks[64][KS_STRIDE];   // K tile, then per-m-tile P staging
    __shared__ float Vs[64][VS_STRIDE];

    const int qrow0 = b * SEQ + qt * 128 + w * 32;
    const float* qbase = qkv + (size_t)qrow0 * QKVN + h * HDIM;

    uint32_t af[2][8][4];
    #pragma unroll
    for (int mt = 0; mt < 2; mt++)
        #pragma unroll
        for (int c = 0; c < 8; c++) {
            const int r0 = mt * 16 + g;
            af[mt][c][0] = __float_as_uint(0.125f * qbase[(size_t)r0       * QKVN + c * 8 + tg]);
            af[mt][c][1] = __float_as_uint(0.125f * qbase[(size_t)(r0 + 8) * QKVN + c * 8 + tg]);
            af[mt][c][2] = __float_as_uint(0.125f * qbase[(size_t)r0       * QKVN + c * 8 + tg + 4]);
            af[mt][c][3] = __float_as_uint(0.125f * qbase[(size_t)(r0 + 8) * QKVN + c * 8 + tg + 4]);
        }

    float o[2][8][4];
    #pragma unroll
    for (int mt = 0; mt < 2; mt++)
        #pragma unroll
        for (int nt = 0; nt < 8; nt++)
            #pragma unroll
            for (int r = 0; r < 4; r++) o[mt][nt][r] = 0.f;
    float mst[2][2] = {{-1e30f, -1e30f}, {-1e30f, -1e30f}};
    float lst[2][2] = {{0.f, 0.f}, {0.f, 0.f}};

    for (int kt = 0; kt < SEQ / 64; kt++) {
        const float* kb = qkv + (size_t)(b * SEQ + kt * 64) * QKVN + DIMC + h * HDIM;
        const float* vb = kb + DIMC;
        #pragma unroll
        for (int it = 0; it < 8; it++) {
            int e4  = it * 128 + tid;
            int row = e4 >> 4;
            int d4  = (e4 & 15) * 4;
            *(float4*)&Ks[row][d4] = *(const float4*)(kb + (size_t)row * QKVN + d4);
            *(float4*)&Vs[row][d4] = *(const float4*)(vb + (size_t)row * QKVN + d4);
        }
        __syncthreads();

        float sc[2][8][4];
        #pragma unroll
        for (int mt = 0; mt < 2; mt++)
            #pragma unroll
            for (int nt = 0; nt < 8; nt++)
                #pragma unroll
                for (int r = 0; r < 4; r++) sc[mt][nt][r] = 0.f;
        #pragma unroll
        for (int c = 0; c < 8; c++) {
            #pragma unroll
            for (int nt = 0; nt < 8; nt++) {
                uint32_t bf[2];
                bf[0] = __float_as_uint(Ks[nt * 8 + g][c * 8 + tg]);
                bf[1] = __float_as_uint(Ks[nt * 8 + g][c * 8 + tg + 4]);
                mma_m16n8k8(sc[0][nt], af[0][c], bf);
                mma_m16n8k8(sc[1][nt], af[1][c], bf);
            }
        }

        float alpha[2][2];
        #pragma unroll
        for (int mt = 0; mt < 2; mt++) {
            float tm0 = -1e30f, tm1 = -1e30f;
            #pragma unroll
            for (int nt = 0; nt < 8; nt++) {
                tm0 = fmaxf(tm0, fmaxf(sc[mt][nt][0], sc[mt][nt][1]));
                tm1 = fmaxf(tm1, fmaxf(sc[mt][nt][2], sc[mt][nt][3]));
            }
            tm0 = fmaxf(tm0, __shfl_xor_sync(0xffffffffu, tm0, 1));
            tm0 = fmaxf(tm0, __shfl_xor_sync(0xffffffffu, tm0, 2));
            tm1 = fmaxf(tm1, __shfl_xor_sync(0xffffffffu, tm1, 1));
            tm1 = fmaxf(tm1, __shfl_xor_sync(0xffffffffu, tm1, 2));
            const float mn0 = fmaxf(mst[mt][0], tm0), mn1 = fmaxf(mst[mt][1], tm1);
            alpha[mt][0] = __expf(mst[mt][0] - mn0);
            alpha[mt][1] = __expf(mst[mt][1] - mn1);
            mst[mt][0] = mn0; mst[mt][1] = mn1;

            float rs0 = 0.f, rs1 = 0.f;
            #pragma unroll
            for (int nt = 0; nt < 8; nt++) {
                sc[mt][nt][0] = __expf(sc[mt][nt][0] - mn0);
                sc[mt][nt][1] = __expf(sc[mt][nt][1] - mn0);
                sc[mt][nt][2] = __expf(sc[mt][nt][2] - mn1);
                sc[mt][nt][3] = __expf(sc[mt][nt][3] - mn1);
                rs0 += sc[mt][nt][0] + sc[mt][nt][1];
                rs1 += sc[mt][nt][2] + sc[mt][nt][3];
            }
            rs0 += __shfl_xor_sync(0xffffffffu, rs0, 1);
            rs0 += __shfl_xor_sync(0xffffffffu, rs0, 2);
            rs1 += __shfl_xor_sync(0xffffffffu, rs1, 1);
            rs1 += __shfl_xor_sync(0xffffffffu, rs1, 2);
            lst[mt][0] = lst[mt][0] * alpha[mt][0] + rs0;
            lst[mt][1] = lst[mt][1] * alpha[mt][1] + rs1;

            #pragma unroll
            for (int nt = 0; nt < 8; nt++) {
                o[mt][nt][0] *= alpha[mt][0]; o[mt][nt][1] *= alpha[mt][0];
                o[mt][nt][2] *= alpha[mt][1]; o[mt][nt][3] *= alpha[mt][1];
            }
        }

        __syncthreads();   // all warps done reading K tile before P overwrites it

        #pragma unroll
        for (int mt = 0; mt < 2; mt++) {
            #pragma unroll
            for (int nt = 0; nt < 8; nt++) {
                *(float2*)&Ks[w * 16 + g][nt * 8 + 2 * tg]     = make_float2(tf32r(sc[mt][nt][0]), tf32r(sc[mt][nt][1]));
                *(float2*)&Ks[w * 16 + g + 8][nt * 8 + 2 * tg] = make_float2(tf32r(sc[mt][nt][2]), tf32r(sc[mt][nt][3]));
            }
            __syncwarp();

            #pragma unroll
            for (int c = 0; c < 8; c++) {
                uint32_t pa[4];
                pa[0] = __float_as_uint(Ks[w * 16 + g][c * 8 + tg]);
                pa[1] = __float_as_uint(Ks[w * 16 + g + 8][c * 8 + tg]);
                pa[2] = __float_as_uint(Ks[w * 16 + g][c * 8 + tg + 4]);
                pa[3] = __float_as_uint(Ks[w * 16 + g + 8][c * 8 + tg + 4]);
                #pragma unroll
                for (int nt = 0; nt < 8; nt++) {
                    uint32_t vbf[2];
                    vbf[0] = __float_as_uint(Vs[c * 8 + tg][nt * 8 + g]);
                    vbf[1] = __float_as_uint(Vs[c * 8 + tg + 4][nt * 8 + g]);
                    mma_m16n8k8(o[mt][nt], pa, vbf);
                }
            }
            __syncwarp();
        }
        __syncthreads();
    }

    #pragma unroll
    for (int mt = 0; mt < 2; mt++) {
        const float inv0 = 1.f / lst[mt][0], inv1 = 1.f / lst[mt][1];
        __half* c0p = ctx + (size_t)(qrow0 + mt * 16 + g)     * DIMC + h * HDIM;
        __half* c1p = ctx + (size_t)(qrow0 + mt * 16 + g + 8) * DIMC + h * HDIM;
        #pragma unroll
        for (int nt = 0; nt < 8; nt++) {
            *(__half2*)&c0p[nt * 8 + 2 * tg] =
                __floats2half2_rn(o[mt][nt][0] * inv0, o[mt][nt][1] * inv0);
            *(__half2*)&c1p[nt * 8 + 2 * tg] =
                __floats2half2_rn(o[mt][nt][2] * inv1, o[mt][nt][3] * inv1);
        }
    }
}

// ---------------- launch ----------------
extern "C" void kernel_launch(void* const* d_in, const int* in_sizes, int n_in,
                              void* d_out, int out_size)
{
    const float* x    = (const float*)d_in[0];
    const float* ln1g = (const float*)d_in[1];
    const float* ln1b = (const float*)d_in[2];
    const float* Wq   = (const float*)d_in[3];
    const float* bq   = (const float*)d_in[4];
    const float* Wk   = (const float*)d_in[5];
    const float* bk   = (const float*)d_in[6];
    const float* Wv   = (const float*)d_in[7];
    const float* bv   = (const float*)d_in[8];
    const float* Wo   = (const float*)d_in[9];
    const float* bo   = (const float*)d_in[10];
    const float* ln2g = (const float*)d_in[11];
    const float* ln2b = (const float*)d_in[12];
    const float* W1   = (const float*)d_in[13];
    const float* b1   = (const float*)d_in[14];
    const float* W2   = (const float*)d_in[15];
    const float* b2   = (const float*)d_in[16];
    float* out = (float*)d_out;

    __half *h, *ctx, *h2, *ffn, *wqkv, *wo, *w1, *w2;
    float *qkv, *x1, *bqkv;
    cudaGetSymbolAddress((void**)&h,    g_h);
    cudaGetSymbolAddress((void**)&qkv,  g_qkv);
    cudaGetSymbolAddress((void**)&ctx,  g_ctx);
    cudaGetSymbolAddress((void**)&x1,   g_x1);
    cudaGetSymbolAddress((void**)&h2,   g_h2);
    cudaGetSymbolAddress((void**)&ffn,  g_ffn);
    cudaGetSymbolAddress((void**)&wqkv, g_wqkv);
    cudaGetSymbolAddress((void**)&bqkv, g_bqkv);
    cudaGetSymbolAddress((void**)&wo,   g_wo);
    cudaGetSymbolAddress((void**)&w1,   g_w1);
    cudaGetSymbolAddress((void**)&w2,   g_w2);

    const dim3 blk(256);
    const dim3 gblk(128);

    // weight prep: transpose fp32 -> fp16 [N][K]
    transpose_f16<<<dim3(DIMC/32, DIMC/32), 256>>>(Wq, wqkv,                   DIMC, DIMC);
    transpose_f16<<<dim3(DIMC/32, DIMC/32), 256>>>(Wk, wqkv + DIMC*DIMC,       DIMC, DIMC);
    transpose_f16<<<dim3(DIMC/32, DIMC/32), 256>>>(Wv, wqkv + 2*DIMC*DIMC,     DIMC, DIMC);
    pack_qkv_b<<<(QKVN + 255) / 256, blk>>>(bq, bk, bv, bqkv);
    transpose_f16<<<dim3(DIMC/32, DIMC/32),    256>>>(Wo, wo, DIMC, DIMC);
    transpose_f16<<<dim3(DIMC/32, HIDDENC/32), 256>>>(W1, w1, DIMC, HIDDENC);
    transpose_f16<<<dim3(HIDDENC/32, DIMC/32), 256>>>(W2, w2, HIDDENC, DIMC);

    const dim3 gqkv(QKVN / 128, NTOK / 128);     // 18 x 128
    const dim3 gd(DIMC / 128, NTOK / 128);       // 6 x 128
    const dim3 gh(HIDDENC / 128, NTOK / 128);    // 24 x 128

    // 1) LN1 -> fp16
    ln_kernel<<<NTOK, blk>>>(x, ln1g, ln1b, h);
    // 2) fused QKV projection (fp16 mma) -> fp32 qkv, tf32-rounded for attention
    gemm_f16<float><<<gqkv, gblk>>>(h, wqkv, bqkv, nullptr, qkv, NTOK, QKVN, DIMC, 0, 1);
    // 3) flash attention (tf32) -> fp16 ctx
    attn_tc<<<dim3(SEQ / 128, HEADSC, BATCH), 128>>>(qkv, ctx);
    // 4) x1 = x + ctx@Wo + bo (fp32 out)
    gemm_f16<float><<<gd, gblk>>>(ctx, wo, bo, x, x1, NTOK, DIMC, DIMC, 0, 0);
    // 5) LN2 -> fp16
    ln_kernel<<<NTOK, blk>>>(x1, ln2g, ln2b, h2);
    // 6) FFN up + exact GELU -> fp16
    gemm_f16<__half><<<gh, gblk>>>(h2, w1, b1, nullptr, ffn, NTOK, HIDDENC, DIMC, 1, 0);
    // 7) out = x1 + ffn@W2 + b2 (fp32 out)
    gemm_f16<float><<<gd, gblk>>>(ffn, w2, b2, x1, out, NTOK, DIMC, HIDDENC, 0, 0);
}

// round 15
// speedup vs baseline: 2.2042x; 1.1241x over previous
#include <cuda_runtime.h>
#include <cuda_fp16.h>
#include <math.h>
#include <stdint.h>

#define DIMC    768
#define HIDDENC 3072
#define SEQ     1024
#define BATCH   16
#define NTOK    (BATCH*SEQ)   // 16384
#define HEADSC  12
#define HDIM    64
#define QKVN    (3*DIMC)      // 2304
#define LN_EPS  1e-5f

// ---------------- scratch (static device arrays; no allocation allowed) ----------------
__device__ __half g_h   [NTOK*DIMC];
__device__ __half g_qkv [NTOK*QKVN];     // fp16 (attention input)
__device__ __half g_ctx [NTOK*DIMC];
__device__ float  g_x1  [NTOK*DIMC];
__device__ __half g_h2  [NTOK*DIMC];
__device__ __half g_ffn [NTOK*HIDDENC];
// fp16 TRANSPOSED weights, [N][K] row-major
__device__ __half g_wqkv[QKVN*DIMC];
__device__ float  g_bqkv[QKVN];
__device__ __half g_wo  [DIMC*DIMC];
__device__ __half g_w1  [HIDDENC*DIMC];
__device__ __half g_w2  [DIMC*HIDDENC];

// ---------------- helpers ----------------
// fp16 m16n8k16, fp32 accumulate
__device__ __forceinline__ void mma_f16(float d[4], const uint32_t a[4], const uint32_t b[2]) {
    asm volatile(
        "mma.sync.aligned.m16n8k16.row.col.f32.f16.f16.f32 "
        "{%0,%1,%2,%3}, {%4,%5,%6,%7}, {%8,%9}, {%0,%1,%2,%3};"
        : "+f"(d[0]), "+f"(d[1]), "+f"(d[2]), "+f"(d[3])
        : "r"(a[0]), "r"(a[1]), "r"(a[2]), "r"(a[3]), "r"(b[0]), "r"(b[1]));
}

__device__ __forceinline__ void cp_async16(void* smem, const void* gmem) {
    uint32_t s = (uint32_t)__cvta_generic_to_shared(smem);
    asm volatile("cp.async.cg.shared.global [%0], [%1], 16;" :: "r"(s), "l"(gmem));
}

__device__ __forceinline__ void store2(float* p, float a, float b) {
    *(float2*)p = make_float2(a, b);
}
__device__ __forceinline__ void store2(__half* p, float a, float b) {
    *(__half2*)p = __floats2half2_rn(a, b);
}

__device__ __forceinline__ uint32_t pack_halves(__half a, __half b) {
    __half2 h = __halves2half2(a, b);
    return *(uint32_t*)&h;
}

// ---------------- weight prep: tiled transpose fp32 [K][N] -> fp16 [N][K] --------------
__global__ __launch_bounds__(256) void transpose_f16(
    const float* __restrict__ in, __half* __restrict__ out, int K, int N)
{
    __shared__ float t[32][33];
    const int k0 = blockIdx.x * 32, n0 = blockIdx.y * 32;
    const int tx = threadIdx.x & 31, ty = threadIdx.x >> 5;   // 32x8
    #pragma unroll
    for (int i = 0; i < 32; i += 8)
        t[ty + i][tx] = in[(size_t)(k0 + ty + i) * N + n0 + tx];
    __syncthreads();
    #pragma unroll
    for (int i = 0; i < 32; i += 8)
        out[(size_t)(n0 + ty + i) * K + k0 + tx] = __float2half_rn(t[tx][ty + i]);
}

__global__ void pack_qkv_b(const float* __restrict__ bq, const float* __restrict__ bk,
                           const float* __restrict__ bv, float* __restrict__ out)
{
    int j = blockIdx.x * 256 + threadIdx.x;
    if (j >= QKVN) return;
    out[j] = (j < DIMC) ? bq[j] : (j < 2 * DIMC) ? bk[j - DIMC] : bv[j - 2 * DIMC];
}

// ---------------- LayerNorm (fp16 output; feeds GEMM A) --------------------------------
__global__ __launch_bounds__(256) void ln_kernel(
    const float* __restrict__ x, const float* __restrict__ g,
    const float* __restrict__ b, __half* __restrict__ out)
{
    const int row = blockIdx.x;
    const int t = threadIdx.x;
    const float* xr = x + (size_t)row * DIMC;
    float v0 = xr[t], v1 = xr[t + 256], v2 = xr[t + 512];
    float s  = v0 + v1 + v2;
    float ss = v0*v0 + v1*v1 + v2*v2;
    #pragma unroll
    for (int o = 16; o; o >>= 1) {
        s  += __shfl_xor_sync(0xffffffffu, s,  o);
        ss += __shfl_xor_sync(0xffffffffu, ss, o);
    }
    __shared__ float sm[8], sm2[8];
    const int w = t >> 5, l = t & 31;
    if (l == 0) { sm[w] = s; sm2[w] = ss; }
    __syncthreads();
    if (w == 0) {
        s  = (l < 8) ? sm[l]  : 0.f;
        ss = (l < 8) ? sm2[l] : 0.f;
        #pragma unroll
        for (int o = 4; o; o >>= 1) {
            s  += __shfl_xor_sync(0xffffffffu, s,  o);
            ss += __shfl_xor_sync(0xffffffffu, ss, o);
        }
        if (l == 0) {
            float mu = s * (1.f / DIMC);
            sm[0]  = mu;
            sm2[0] = rsqrtf(ss * (1.f / DIMC) - mu * mu + LN_EPS);
        }
    }
    __syncthreads();
    const float mu = sm[0], rstd = sm2[0];
    __half* orow = out + (size_t)row * DIMC;
    orow[t]       = __float2half_rn((v0 - mu) * rstd * g[t]       + b[t]);
    orow[t + 256] = __float2half_rn((v1 - mu) * rstd * g[t + 256] + b[t + 256]);
    orow[t + 512] = __float2half_rn((v2 - mu) * rstd * g[t + 512] + b[t + 512]);
}

// ---------------- FP16 tensor-core GEMM (R13 proven) -----------------------------------
#define AS_STRIDE 40
#define A_TILE (128*AS_STRIDE)

template<typename OutT>
__global__ __launch_bounds__(128) void gemm_f16(
    const __half* __restrict__ A, const __half* __restrict__ Bt,
    const float* __restrict__ bias, const float* __restrict__ res,
    OutT* __restrict__ C, int M, int N, int K, int do_gelu)
{
    __shared__ alignas(16) __half As[2][A_TILE];
    __shared__ alignas(16) __half Bs[2][A_TILE];

    const int bx = blockIdx.x * 128;
    const int by = blockIdx.y * 128;
    const int tid = threadIdx.x;
    const int wid = tid >> 5;
    const int lane = tid & 31;
    const int g  = lane >> 2;
    const int tg = lane & 3;

    const int wm = (wid & 1) * 64;
    const int wn = (wid >> 1) * 64;

    float acc[4][8][4];
    #pragma unroll
    for (int mt = 0; mt < 4; mt++)
        #pragma unroll
        for (int nt = 0; nt < 8; nt++)
            #pragma unroll
            for (int r = 0; r < 4; r++) acc[mt][nt][r] = 0.f;

    const int KT = K / 32;

    auto load_stage = [&](int st, int k0) {
        #pragma unroll
        for (int i = 0; i < 4; i++) {
            const int idx = tid + 128 * i;
            const int row = idx >> 2;
            const int ch  = (idx & 3) * 8;
            cp_async16(&As[st][row * AS_STRIDE + ch], A  + (size_t)(by + row) * K + k0 + ch);
            cp_async16(&Bs[st][row * AS_STRIDE + ch], Bt + (size_t)(bx + row) * K + k0 + ch);
        }
        asm volatile("cp.async.commit_group;");
    };

    load_stage(0, 0);

    for (int kt = 0; kt < KT; kt++) {
        const int s = kt & 1;
        if (kt + 1 < KT) {
            load_stage(s ^ 1, (kt + 1) * 32);
            asm volatile("cp.async.wait_group 1;");
        } else {
            asm volatile("cp.async.wait_group 0;");
        }
        __syncthreads();

        const __half* as = As[s];
        const __half* bs = Bs[s];
        #pragma unroll
        for (int kk = 0; kk < 32; kk += 16) {
            uint32_t af[4][4];
            #pragma unroll
            for (int mt = 0; mt < 4; mt++) {
                const int m0 = wm + mt * 16 + g;
                af[mt][0] = *(const uint32_t*)&as[m0 * AS_STRIDE + kk + 2 * tg];
                af[mt][1] = *(const uint32_t*)&as[(m0 + 8) * AS_STRIDE + kk + 2 * tg];
                af[mt][2] = *(const uint32_t*)&as[m0 * AS_STRIDE + kk + 2 * tg + 8];
                af[mt][3] = *(const uint32_t*)&as[(m0 + 8) * AS_STRIDE + kk + 2 * tg + 8];
            }
            uint32_t bf[8][2];
            #pragma unroll
            for (int nt = 0; nt < 8; nt++) {
                const int n0 = wn + nt * 8 + g;
                bf[nt][0] = *(const uint32_t*)&bs[n0 * AS_STRIDE + kk + 2 * tg];
                bf[nt][1] = *(const uint32_t*)&bs[n0 * AS_STRIDE + kk + 2 * tg + 8];
            }
            #pragma unroll
            for (int mt = 0; mt < 4; mt++)
                #pragma unroll
                for (int nt = 0; nt < 8; nt++)
                    mma_f16(acc[mt][nt], af[mt], bf[nt]);
        }
        __syncthreads();
    }

    #pragma unroll
    for (int mt = 0; mt < 4; mt++) {
        const int r0 = by + wm + mt * 16 + g;
        #pragma unroll
        for (int nt = 0; nt < 8; nt++) {
            const int c0 = bx + wn + nt * 8 + tg * 2;
            const float b0 = bias[c0], b1 = bias[c0 + 1];
            float v00 = acc[mt][nt][0] + b0;
            float v01 = acc[mt][nt][1] + b1;
            float v10 = acc[mt][nt][2] + b0;
            float v11 = acc[mt][nt][3] + b1;
            if (do_gelu) {
                v00 = 0.5f * v00 * (1.0f + erff(v00 * 0.70710678118654752f));
                v01 = 0.5f * v01 * (1.0f + erff(v01 * 0.70710678118654752f));
                v10 = 0.5f * v10 * (1.0f + erff(v10 * 0.70710678118654752f));
                v11 = 0.5f * v11 * (1.0f + erff(v11 * 0.70710678118654752f));
            }
            if (res) {
                const float2 r01 = *(const float2*)&res[(size_t)r0 * N + c0];
                const float2 r11 = *(const float2*)&res[(size_t)(r0 + 8) * N + c0];
                v00 += r01.x; v01 += r01.y;
                v10 += r11.x; v11 += r11.y;
            }
            store2(&C[(size_t)r0 * N + c0],       v00, v01);
            store2(&C[(size_t)(r0 + 8) * N + c0], v10, v11);
        }
    }
}

// ---------------- FP16 flash attention: 128 q-rows/block, m16n8k16 ---------------------
// qkv fp16 [NTOK][2304]: q at h*64, k at 768+h*64, v at 1536+h*64.
// Warp w owns q-rows w*32..w*32+31 (2 m-tiles). KV tiles 64 rows.
// S scaled by 1/8 post-MMA in fp32 (exact).
#define KST 72    // halves stride for Ks/Vs
#define PST 72    // halves stride for Ps

__global__ __launch_bounds__(128) void attn_f16(
    const __half* __restrict__ qkv, __half* __restrict__ ctx)
{
    __shared__ __half Ks[64][KST];
    __shared__ __half Vs[64][KST];
    __shared__ __half Ps[128][PST];

    const int qt = blockIdx.x, h = blockIdx.y, b = blockIdx.z;
    const int tid = threadIdx.x, w = tid >> 5, lane = tid & 31;
    const int g = lane >> 2, tg = lane & 3;

    const int qrow0 = b * SEQ + qt * 128 + w * 32;
    const __half* qbase = qkv + (size_t)qrow0 * QKVN + h * HDIM;

    // Q fragments for 2 m-tiles (fp16, unscaled; scale applied to S)
    uint32_t af[2][4][4];
    #pragma unroll
    for (int mt = 0; mt < 2; mt++)
        #pragma unroll
        for (int c = 0; c < 4; c++) {
            const int r0 = mt * 16 + g;
            af[mt][c][0] = *(const uint32_t*)&qbase[(size_t)r0       * QKVN + c * 16 + 2 * tg];
            af[mt][c][1] = *(const uint32_t*)&qbase[(size_t)(r0 + 8) * QKVN + c * 16 + 2 * tg];
            af[mt][c][2] = *(const uint32_t*)&qbase[(size_t)r0       * QKVN + c * 16 + 2 * tg + 8];
            af[mt][c][3] = *(const uint32_t*)&qbase[(size_t)(r0 + 8) * QKVN + c * 16 + 2 * tg + 8];
        }

    float o[2][8][4];
    #pragma unroll
    for (int mt = 0; mt < 2; mt++)
        #pragma unroll
        for (int nt = 0; nt < 8; nt++)
            #pragma unroll
            for (int r = 0; r < 4; r++) o[mt][nt][r] = 0.f;
    float mst[2][2] = {{-1e30f, -1e30f}, {-1e30f, -1e30f}};
    float lst[2][2] = {{0.f, 0.f}, {0.f, 0.f}};

    for (int kt = 0; kt < SEQ / 64; kt++) {
        const __half* kb = qkv + (size_t)(b * SEQ + kt * 64) * QKVN + DIMC + h * HDIM;
        const __half* vb = kb + DIMC;
        // 64 rows x 64 halves (128B) per tile: 512 uint4 loads over 128 threads x 4 iters
        #pragma unroll
        for (int it = 0; it < 4; it++) {
            int idx = it * 128 + tid;          // 0..511
            int row = idx >> 3;
            int c8  = (idx & 7) * 8;           // halves
            *(uint4*)&Ks[row][c8] = *(const uint4*)(kb + (size_t)row * QKVN + c8);
            *(uint4*)&Vs[row][c8] = *(const uint4*)(vb + (size_t)row * QKVN + c8);
        }
        __syncthreads();

        // S = Q @ K^T (then *1/8); K fragments shared across m-tiles
        float sc[2][8][4];
        #pragma unroll
        for (int mt = 0; mt < 2; mt++)
            #pragma unroll
            for (int nt = 0; nt < 8; nt++)
                #pragma unroll
                for (int r = 0; r < 4; r++) sc[mt][nt][r] = 0.f;
        #pragma unroll
        for (int c = 0; c < 4; c++) {
            #pragma unroll
            for (int nt = 0; nt < 8; nt++) {
                uint32_t bf[2];
                bf[0] = *(const uint32_t*)&Ks[nt * 8 + g][c * 16 + 2 * tg];
                bf[1] = *(const uint32_t*)&Ks[nt * 8 + g][c * 16 + 2 * tg + 8];
                mma_f16(sc[0][nt], af[0][c], bf);
                mma_f16(sc[1][nt], af[1][c], bf);
            }
        }

        // online softmax per m-tile + P staging (fp16)
        #pragma unroll
        for (int mt = 0; mt < 2; mt++) {
            float tm0 = -1e30f, tm1 = -1e30f;
            #pragma unroll
            for (int nt = 0; nt < 8; nt++) {
                #pragma unroll
                for (int r = 0; r < 4; r++) sc[mt][nt][r] *= 0.125f;
                tm0 = fmaxf(tm0, fmaxf(sc[mt][nt][0], sc[mt][nt][1]));
                tm1 = fmaxf(tm1, fmaxf(sc[mt][nt][2], sc[mt][nt][3]));
            }
            tm0 = fmaxf(tm0, __shfl_xor_sync(0xffffffffu, tm0, 1));
            tm0 = fmaxf(tm0, __shfl_xor_sync(0xffffffffu, tm0, 2));
            tm1 = fmaxf(tm1, __shfl_xor_sync(0xffffffffu, tm1, 1));
            tm1 = fmaxf(tm1, __shfl_xor_sync(0xffffffffu, tm1, 2));
            const float mn0 = fmaxf(mst[mt][0], tm0), mn1 = fmaxf(mst[mt][1], tm1);
            const float a0 = __expf(mst[mt][0] - mn0), a1 = __expf(mst[mt][1] - mn1);
            mst[mt][0] = mn0; mst[mt][1] = mn1;

            float rs0 = 0.f, rs1 = 0.f;
            #pragma unroll
            for (int nt = 0; nt < 8; nt++) {
                sc[mt][nt][0] = __expf(sc[mt][nt][0] - mn0);
                sc[mt][nt][1] = __expf(sc[mt][nt][1] - mn0);
                sc[mt][nt][2] = __expf(sc[mt][nt][2] - mn1);
                sc[mt][nt][3] = __expf(sc[mt][nt][3] - mn1);
                rs0 += sc[mt][nt][0] + sc[mt][nt][1];
                rs1 += sc[mt][nt][2] + sc[mt][nt][3];
            }
            rs0 += __shfl_xor_sync(0xffffffffu, rs0, 1);
            rs0 += __shfl_xor_sync(0xffffffffu, rs0, 2);
            rs1 += __shfl_xor_sync(0xffffffffu, rs1, 1);
            rs1 += __shfl_xor_sync(0xffffffffu, rs1, 2);
            lst[mt][0] = lst[mt][0] * a0 + rs0;
            lst[mt][1] = lst[mt][1] * a1 + rs1;

            #pragma unroll
            for (int nt = 0; nt < 8; nt++) {
                o[mt][nt][0] *= a0; o[mt][nt][1] *= a0;
                o[mt][nt][2] *= a1; o[mt][nt][3] *= a1;
            }

            const int pr = w * 32 + mt * 16;
            #pragma unroll
            for (int nt = 0; nt < 8; nt++) {
                *(__half2*)&Ps[pr + g][nt * 8 + 2 * tg]     = __floats2half2_rn(sc[mt][nt][0], sc[mt][nt][1]);
                *(__half2*)&Ps[pr + g + 8][nt * 8 + 2 * tg] = __floats2half2_rn(sc[mt][nt][2], sc[mt][nt][3]);
            }
        }
        __syncwarp();

        // O += P @ V ; V B-fragments packed from two half reads, reused across m-tiles
        const int pr = w * 32;
        #pragma unroll
        for (int c = 0; c < 4; c++) {
            uint32_t pa0[4], pa1[4];
            pa0[0] = *(const uint32_t*)&Ps[pr + g][c * 16 + 2 * tg];
            pa0[1] = *(const uint32_t*)&Ps[pr + g + 8][c * 16 + 2 * tg];
            pa0[2] = *(const uint32_t*)&Ps[pr + g][c * 16 + 2 * tg + 8];
            pa0[3] = *(const uint32_t*)&Ps[pr + g + 8][c * 16 + 2 * tg + 8];
            pa1[0] = *(const uint32_t*)&Ps[pr + 16 + g][c * 16 + 2 * tg];
            pa1[1] = *(const uint32_t*)&Ps[pr + 24 + g][c * 16 + 2 * tg];
            pa1[2] = *(const uint32_t*)&Ps[pr + 16 + g][c * 16 + 2 * tg + 8];
            pa1[3] = *(const uint32_t*)&Ps[pr + 24 + g][c * 16 + 2 * tg + 8];
            #pragma unroll
            for (int nt = 0; nt < 8; nt++) {
                const int n0 = nt * 8 + g;
                uint32_t vbf[2];
                vbf[0] = pack_halves(Vs[c * 16 + 2 * tg][n0],     Vs[c * 16 + 2 * tg + 1][n0]);
                vbf[1] = pack_halves(Vs[c * 16 + 2 * tg + 8][n0], Vs[c * 16 + 2 * tg + 9][n0]);
                mma_f16(o[0][nt], pa0, vbf);
                mma_f16(o[1][nt], pa1, vbf);
            }
        }
        __syncthreads();   // Ks/Vs consumed; safe to overwrite next kt
    }

    #pragma unroll
    for (int mt = 0; mt < 2; mt++) {
        const float inv0 = 1.f / lst[mt][0], inv1 = 1.f / lst[mt][1];
        __half* c0p = ctx + (size_t)(qrow0 + mt * 16 + g)     * DIMC + h * HDIM;
        __half* c1p = ctx + (size_t)(qrow0 + mt * 16 + g + 8) * DIMC + h * HDIM;
        #pragma unroll
        for (int nt = 0; nt < 8; nt++) {
            *(__half2*)&c0p[nt * 8 + 2 * tg] =
                __floats2half2_rn(o[mt][nt][0] * inv0, o[mt][nt][1] * inv0);
            *(__half2*)&c1p[nt * 8 + 2 * tg] =
                __floats2half2_rn(o[mt][nt][2] * inv1, o[mt][nt][3] * inv1);
        }
    }
}

// ---------------- launch ----------------
extern "C" void kernel_launch(void* const* d_in, const int* in_sizes, int n_in,
                              void* d_out, int out_size)
{
    const float* x    = (const float*)d_in[0];
    const float* ln1g = (const float*)d_in[1];
    const float* ln1b = (const float*)d_in[2];
    const float* Wq   = (const float*)d_in[3];
    const float* bq   = (const float*)d_in[4];
    const float* Wk   = (const float*)d_in[5];
    const float* bk   = (const float*)d_in[6];
    const float* Wv   = (const float*)d_in[7];
    const float* bv   = (const float*)d_in[8];
    const float* Wo   = (const float*)d_in[9];
    const float* bo   = (const float*)d_in[10];
    const float* ln2g = (const float*)d_in[11];
    const float* ln2b = (const float*)d_in[12];
    const float* W1   = (const float*)d_in[13];
    const float* b1   = (const float*)d_in[14];
    const float* W2   = (const float*)d_in[15];
    const float* b2   = (const float*)d_in[16];
    float* out = (float*)d_out;

    __half *h, *qkv, *ctx, *h2, *ffn, *wqkv, *wo, *w1, *w2;
    float *x1, *bqkv;
    cudaGetSymbolAddress((void**)&h,    g_h);
    cudaGetSymbolAddress((void**)&qkv,  g_qkv);
    cudaGetSymbolAddress((void**)&ctx,  g_ctx);
    cudaGetSymbolAddress((void**)&x1,   g_x1);
    cudaGetSymbolAddress((void**)&h2,   g_h2);
    cudaGetSymbolAddress((void**)&ffn,  g_ffn);
    cudaGetSymbolAddress((void**)&wqkv, g_wqkv);
    cudaGetSymbolAddress((void**)&bqkv, g_bqkv);
    cudaGetSymbolAddress((void**)&wo,   g_wo);
    cudaGetSymbolAddress((void**)&w1,   g_w1);
    cudaGetSymbolAddress((void**)&w2,   g_w2);

    const dim3 blk(256);
    const dim3 gblk(128);

    // weight prep: transpose fp32 -> fp16 [N][K]
    transpose_f16<<<dim3(DIMC/32, DIMC/32), 256>>>(Wq, wqkv,                   DIMC, DIMC);
    transpose_f16<<<dim3(DIMC/32, DIMC/32), 256>>>(Wk, wqkv + DIMC*DIMC,       DIMC, DIMC);
    transpose_f16<<<dim3(DIMC/32, DIMC/32), 256>>>(Wv, wqkv + 2*DIMC*DIMC,     DIMC, DIMC);
    pack_qkv_b<<<(QKVN + 255) / 256, blk>>>(bq, bk, bv, bqkv);
    transpose_f16<<<dim3(DIMC/32, DIMC/32),    256>>>(Wo, wo, DIMC, DIMC);
    transpose_f16<<<dim3(DIMC/32, HIDDENC/32), 256>>>(W1, w1, DIMC, HIDDENC);
    transpose_f16<<<dim3(HIDDENC/32, DIMC/32), 256>>>(W2, w2, HIDDENC, DIMC);

    const dim3 gqkv(QKVN / 128, NTOK / 128);     // 18 x 128
    const dim3 gd(DIMC / 128, NTOK / 128);       // 6 x 128
    const dim3 gh(HIDDENC / 128, NTOK / 128);    // 24 x 128

    // 1) LN1 -> fp16
    ln_kernel<<<NTOK, blk>>>(x, ln1g, ln1b, h);
    // 2) fused QKV projection -> fp16 qkv
    gemm_f16<__half><<<gqkv, gblk>>>(h, wqkv, bqkv, nullptr, qkv, NTOK, QKVN, DIMC, 0);
    // 3) fp16 flash attention -> fp16 ctx
    attn_f16<<<dim3(SEQ / 128, HEADSC, BATCH), 128>>>(qkv, ctx);
    // 4) x1 = x + ctx@Wo + bo (fp32 out)
    gemm_f16<float><<<gd, gblk>>>(ctx, wo, bo, x, x1, NTOK, DIMC, DIMC, 0);
    // 5) LN2 -> fp16
    ln_kernel<<<NTOK, blk>>>(x1, ln2g, ln2b, h2);
    // 6) FFN up + exact GELU -> fp16
    gemm_f16<__half><<<gh, gblk>>>(h2, w1, b1, nullptr, ffn, NTOK, HIDDENC, DIMC, 1);
    // 7) out = x1 + ffn@W2 + b2 (fp32 out)
    gemm_f16<float><<<gd, gblk>>>(ffn, w2, b2, x1, out, NTOK, DIMC, HIDDENC, 0);
}

// round 17
// speedup vs baseline: 2.5909x; 1.1754x over previous
#include <cuda_runtime.h>
#include <cuda_fp16.h>
#include <math.h>
#include <stdint.h>

#define DIMC    768
#define HIDDENC 3072
#define SEQ     1024
#define BATCH   16
#define NTOK    (BATCH*SEQ)   // 16384
#define HEADSC  12
#define HDIM    64
#define QKVN    (3*DIMC)      // 2304
#define LN_EPS  1e-5f

// ---------------- scratch (static device arrays; no allocation allowed) ----------------
__device__ __half g_h   [NTOK*DIMC];
__device__ __half g_qkv [NTOK*QKVN];
__device__ __half g_ctx [NTOK*DIMC];
__device__ float  g_x1  [NTOK*DIMC];
__device__ __half g_h2  [NTOK*DIMC];
__device__ __half g_ffn [NTOK*HIDDENC];
__device__ __half g_wqkv[QKVN*DIMC];
__device__ float  g_bqkv[QKVN];
__device__ __half g_wo  [DIMC*DIMC];
__device__ __half g_w1  [HIDDENC*DIMC];
__device__ __half g_w2  [DIMC*HIDDENC];

// ---------------- helpers ----------------
__device__ __forceinline__ void mma_f16(float d[4], const uint32_t a[4], const uint32_t b[2]) {
    asm volatile(
        "mma.sync.aligned.m16n8k16.row.col.f32.f16.f16.f32 "
        "{%0,%1,%2,%3}, {%4,%5,%6,%7}, {%8,%9}, {%0,%1,%2,%3};"
        : "+f"(d[0]), "+f"(d[1]), "+f"(d[2]), "+f"(d[3])
        : "r"(a[0]), "r"(a[1]), "r"(a[2]), "r"(a[3]), "r"(b[0]), "r"(b[1]));
}

__device__ __forceinline__ void ldm_x4(uint32_t r[4], uint32_t addr) {
    asm volatile("ldmatrix.sync.aligned.m8n8.x4.shared.b16 {%0,%1,%2,%3}, [%4];"
        : "=r"(r[0]), "=r"(r[1]), "=r"(r[2]), "=r"(r[3]) : "r"(addr));
}
__device__ __forceinline__ void ldm_x4_trans(uint32_t r[4], uint32_t addr) {
    asm volatile("ldmatrix.sync.aligned.m8n8.x4.trans.shared.b16 {%0,%1,%2,%3}, [%4];"
        : "=r"(r[0]), "=r"(r[1]), "=r"(r[2]), "=r"(r[3]) : "r"(addr));
}

__device__ __forceinline__ void cp_async16(void* smem, const void* gmem) {
    uint32_t s = (uint32_t)__cvta_generic_to_shared(smem);
    asm volatile("cp.async.cg.shared.global [%0], [%1], 16;" :: "r"(s), "l"(gmem));
}

__device__ __forceinline__ void store2(float* p, float a, float b) {
    *(float2*)p = make_float2(a, b);
}
__device__ __forceinline__ void store2(__half* p, float a, float b) {
    *(__half2*)p = __floats2half2_rn(a, b);
}

// ---------------- weight prep: tiled transpose fp32 [K][N] -> fp16 [N][K] --------------
__global__ __launch_bounds__(256) void transpose_f16(
    const float* __restrict__ in, __half* __restrict__ out, int K, int N)
{
    __shared__ float t[32][33];
    const int k0 = blockIdx.x * 32, n0 = blockIdx.y * 32;
    const int tx = threadIdx.x & 31, ty = threadIdx.x >> 5;
    #pragma unroll
    for (int i = 0; i < 32; i += 8)
        t[ty + i][tx] = in[(size_t)(k0 + ty + i) * N + n0 + tx];
    __syncthreads();
    #pragma unroll
    for (int i = 0; i < 32; i += 8)
        out[(size_t)(n0 + ty + i) * K + k0 + tx] = __float2half_rn(t[tx][ty + i]);
}

__global__ void pack_qkv_b(const float* __restrict__ bq, const float* __restrict__ bk,
                           const float* __restrict__ bv, float* __restrict__ out)
{
    int j = blockIdx.x * 256 + threadIdx.x;
    if (j >= QKVN) return;
    out[j] = (j < DIMC) ? bq[j] : (j < 2 * DIMC) ? bk[j - DIMC] : bv[j - 2 * DIMC];
}

// ---------------- LayerNorm (fp16 output) ----------------------------------------------
__global__ __launch_bounds__(256) void ln_kernel(
    const float* __restrict__ x, const float* __restrict__ g,
    const float* __restrict__ b, __half* __restrict__ out)
{
    const int row = blockIdx.x;
    const int t = threadIdx.x;
    const float* xr = x + (size_t)row * DIMC;
    float v0 = xr[t], v1 = xr[t + 256], v2 = xr[t + 512];
    float s  = v0 + v1 + v2;
    float ss = v0*v0 + v1*v1 + v2*v2;
    #pragma unroll
    for (int o = 16; o; o >>= 1) {
        s  += __shfl_xor_sync(0xffffffffu, s,  o);
        ss += __shfl_xor_sync(0xffffffffu, ss, o);
    }
    __shared__ float sm[8], sm2[8];
    const int w = t >> 5, l = t & 31;
    if (l == 0) { sm[w] = s; sm2[w] = ss; }
    __syncthreads();
    if (w == 0) {
        s  = (l < 8) ? sm[l]  : 0.f;
        ss = (l < 8) ? sm2[l] : 0.f;
        #pragma unroll
        for (int o = 4; o; o >>= 1) {
            s  += __shfl_xor_sync(0xffffffffu, s,  o);
            ss += __shfl_xor_sync(0xffffffffu, ss, o);
        }
        if (l == 0) {
            float mu = s * (1.f / DIMC);
            sm[0]  = mu;
            sm2[0] = rsqrtf(ss * (1.f / DIMC) - mu * mu + LN_EPS);
        }
    }
    __syncthreads();
    const float mu = sm[0], rstd = sm2[0];
    __half* orow = out + (size_t)row * DIMC;
    orow[t]       = __float2half_rn((v0 - mu) * rstd * g[t]       + b[t]);
    orow[t + 256] = __float2half_rn((v1 - mu) * rstd * g[t + 256] + b[t + 256]);
    orow[t + 512] = __float2half_rn((v2 - mu) * rstd * g[t + 512] + b[t + 512]);
}

// ---------------- FP16 GEMM: ldmatrix fragments, K=64 stages ---------------------------
// A [M,K] fp16 row-major, Bt [N,K] fp16 row-major. Block 128x128, 4 warps (2x2), 64x64.
#define GST 72                       // halves stride: 64 k + 8 pad (144B rows; banks 4r mod 32)
#define GTILE (128*GST)              // halves per tile
#define GEMM_SMEM (4*GTILE*2)        // 2 stages * (A+B) = 73728 bytes

template<typename OutT>
__global__ __launch_bounds__(128) void gemm_f16(
    const __half* __restrict__ A, const __half* __restrict__ Bt,
    const float* __restrict__ bias, const float* __restrict__ res,
    OutT* __restrict__ C, int M, int N, int K, int do_gelu)
{
    extern __shared__ __half smem[];
    __half* const AsB = smem;                // stage s at s*GTILE
    __half* const BsB = smem + 2 * GTILE;

    const int bx = blockIdx.x * 128;
    const int by = blockIdx.y * 128;
    const int tid = threadIdx.x;
    const int wid = tid >> 5;
    const int lane = tid & 31;

    const int wm = (wid & 1) * 64;
    const int wn = (wid >> 1) * 64;

    // ldmatrix lane->tile-row mappings (match mma fragment reg order)
    const int aRow = (lane & 7) + ((lane >> 3) & 1) * 8;   // + mt*16 + wm
    const int aCol = (lane >> 4) * 8;                       // + kk
    const int bRow = (lane & 7) + (lane >> 4) * 8;          // + ntp*16 + wn
    const int bCol = ((lane >> 3) & 1) * 8;                 // + kk

    float acc[4][8][4];
    #pragma unroll
    for (int mt = 0; mt < 4; mt++)
        #pragma unroll
        for (int nt = 0; nt < 8; nt++)
            #pragma unroll
            for (int r = 0; r < 4; r++) acc[mt][nt][r] = 0.f;

    const int KT = K / 64;

    auto load_stage = [&](int st, int k0) {
        __half* As = AsB + st * GTILE;
        __half* Bs = BsB + st * GTILE;
        #pragma unroll
        for (int i = 0; i < 8; i++) {
            const int idx = tid + 128 * i;       // 0..1023
            const int row = idx >> 3;
            const int ch  = (idx & 7) * 8;       // halves
            cp_async16(&As[row * GST + ch], A  + (size_t)(by + row) * K + k0 + ch);
            cp_async16(&Bs[row * GST + ch], Bt + (size_t)(bx + row) * K + k0 + ch);
        }
        asm volatile("cp.async.commit_group;");
    };

    load_stage(0, 0);

    for (int kt = 0; kt < KT; kt++) {
        const int s = kt & 1;
        if (kt + 1 < KT) {
            load_stage(s ^ 1, (kt + 1) * 64);
            asm volatile("cp.async.wait_group 1;");
        } else {
            asm volatile("cp.async.wait_group 0;");
        }
        __syncthreads();

        const uint32_t aBase = (uint32_t)__cvta_generic_to_shared(AsB + s * GTILE);
        const uint32_t bBase = (uint32_t)__cvta_generic_to_shared(BsB + s * GTILE);

        #pragma unroll
        for (int kk = 0; kk < 64; kk += 16) {
            uint32_t af[4][4];
            #pragma unroll
            for (int mt = 0; mt < 4; mt++)
                ldm_x4(af[mt], aBase + ((wm + mt * 16 + aRow) * GST + kk + aCol) * 2);
            uint32_t bf[8][2];
            #pragma unroll
            for (int ntp = 0; ntp < 4; ntp++) {
                uint32_t r4[4];
                ldm_x4(r4, bBase + ((wn + ntp * 16 + bRow) * GST + kk + bCol) * 2);
                bf[ntp * 2][0] = r4[0]; bf[ntp * 2][1] = r4[1];
                bf[ntp * 2 + 1][0] = r4[2]; bf[ntp * 2 + 1][1] = r4[3];
            }
            #pragma unroll
            for (int mt = 0; mt < 4; mt++)
                #pragma unroll
                for (int nt = 0; nt < 8; nt++)
                    mma_f16(acc[mt][nt], af[mt], bf[nt]);
        }
        __syncthreads();
    }

    const int g  = lane >> 2;
    const int tg = lane & 3;
    #pragma unroll
    for (int mt = 0; mt < 4; mt++) {
        const int r0 = by + wm + mt * 16 + g;
        #pragma unroll
        for (int nt = 0; nt < 8; nt++) {
            const int c0 = bx + wn + nt * 8 + tg * 2;
            const float b0 = bias[c0], b1 = bias[c0 + 1];
            float v00 = acc[mt][nt][0] + b0;
            float v01 = acc[mt][nt][1] + b1;
            float v10 = acc[mt][nt][2] + b0;
            float v11 = acc[mt][nt][3] + b1;
            if (do_gelu) {
                v00 = 0.5f * v00 * (1.0f + erff(v00 * 0.70710678118654752f));
                v01 = 0.5f * v01 * (1.0f + erff(v01 * 0.70710678118654752f));
                v10 = 0.5f * v10 * (1.0f + erff(v10 * 0.70710678118654752f));
                v11 = 0.5f * v11 * (1.0f + erff(v11 * 0.70710678118654752f));
            }
            if (res) {
                const float2 r01 = *(const float2*)&res[(size_t)r0 * N + c0];
                const float2 r11 = *(const float2*)&res[(size_t)(r0 + 8) * N + c0];
                v00 += r01.x; v01 += r01.y;
                v10 += r11.x; v11 += r11.y;
            }
            store2(&C[(size_t)r0 * N + c0],       v00, v01);
            store2(&C[(size_t)(r0 + 8) * N + c0], v10, v11);
        }
    }
}

// ---------------- FP16 flash attention: ldmatrix fragments -----------------------------
// 128 q-rows/block, 4 warps; warp w owns rows w*32..w*32+31 (2 m-tiles).
#define KST 72
#define PST 72

__global__ __launch_bounds__(128) void attn_f16(
    const __half* __restrict__ qkv, __half* __restrict__ ctx)
{
    __shared__ __half Ks[64][KST];
    __shared__ __half Vs[64][KST];
    __shared__ __half Ps[128][PST];

    const int qt = blockIdx.x, h = blockIdx.y, b = blockIdx.z;
    const int tid = threadIdx.x, w = tid >> 5, lane = tid & 31;
    const int g = lane >> 2, tg = lane & 3;

    // ldmatrix lane mappings
    const int aRow = (lane & 7) + ((lane >> 3) & 1) * 8;   // A-style (P)
    const int aCol = (lane >> 4) * 8;
    const int bRow = (lane & 7) + (lane >> 4) * 8;          // B-style (K)
    const int bCol = ((lane >> 3) & 1) * 8;
    // V trans mapping
    const int vKey = (lane & 7) + ((lane >> 3) & 1) * 8;    // + c*16
    const int vCol = (lane >> 4) * 8;                        // + ntp*16

    const int qrow0 = b * SEQ + qt * 128 + w * 32;
    const __half* qbase = qkv + (size_t)qrow0 * QKVN + h * HDIM;

    uint32_t af[2][4][4];
    #pragma unroll
    for (int mt = 0; mt < 2; mt++)
        #pragma unroll
        for (int c = 0; c < 4; c++) {
            const int r0 = mt * 16 + g;
            af[mt][c][0] = *(const uint32_t*)&qbase[(size_t)r0       * QKVN + c * 16 + 2 * tg];
            af[mt][c][1] = *(const uint32_t*)&qbase[(size_t)(r0 + 8) * QKVN + c * 16 + 2 * tg];
            af[mt][c][2] = *(const uint32_t*)&qbase[(size_t)r0       * QKVN + c * 16 + 2 * tg + 8];
            af[mt][c][3] = *(const uint32_t*)&qbase[(size_t)(r0 + 8) * QKVN + c * 16 + 2 * tg + 8];
        }

    float o[2][8][4];
    #pragma unroll
    for (int mt = 0; mt < 2; mt++)
        #pragma unroll
        for (int nt = 0; nt < 8; nt++)
            #pragma unroll
            for (int r = 0; r < 4; r++) o[mt][nt][r] = 0.f;
    float mst[2][2] = {{-1e30f, -1e30f}, {-1e30f, -1e30f}};
    float lst[2][2] = {{0.f, 0.f}, {0.f, 0.f}};

    const uint32_t ksBase = (uint32_t)__cvta_generic_to_shared(&Ks[0][0]);
    const uint32_t vsBase = (uint32_t)__cvta_generic_to_shared(&Vs[0][0]);
    const uint32_t psBase = (uint32_t)__cvta_generic_to_shared(&Ps[0][0]);

    for (int kt = 0; kt < SEQ / 64; kt++) {
        const __half* kb = qkv + (size_t)(b * SEQ + kt * 64) * QKVN + DIMC + h * HDIM;
        const __half* vb = kb + DIMC;
        #pragma unroll
        for (int it = 0; it < 4; it++) {
            int idx = it * 128 + tid;
            int row = idx >> 3;
            int c8  = (idx & 7) * 8;
            *(uint4*)&Ks[row][c8] = *(const uint4*)(kb + (size_t)row * QKVN + c8);
            *(uint4*)&Vs[row][c8] = *(const uint4*)(vb + (size_t)row * QKVN + c8);
        }
        __syncthreads();

        // S = Q @ K^T (scaled by 1/8 after)
        float sc[2][8][4];
        #pragma unroll
        for (int mt = 0; mt < 2; mt++)
            #pragma unroll
            for (int nt = 0; nt < 8; nt++)
                #pragma unroll
                for (int r = 0; r < 4; r++) sc[mt][nt][r] = 0.f;
        #pragma unroll
        for (int c = 0; c < 4; c++) {
            #pragma unroll
            for (int ntp = 0; ntp < 4; ntp++) {
                uint32_t r4[4];
                ldm_x4(r4, ksBase + ((ntp * 16 + bRow) * KST + c * 16 + bCol) * 2);
                uint32_t b0[2] = {r4[0], r4[1]}, b1[2] = {r4[2], r4[3]};
                mma_f16(sc[0][ntp * 2],     af[0][c], b0);
                mma_f16(sc[0][ntp * 2 + 1], af[0][c], b1);
                mma_f16(sc[1][ntp * 2],     af[1][c], b0);
                mma_f16(sc[1][ntp * 2 + 1], af[1][c], b1);
            }
        }

        // online softmax + P staging (fp16)
        #pragma unroll
        for (int mt = 0; mt < 2; mt++) {
            float tm0 = -1e30f, tm1 = -1e30f;
            #pragma unroll
            for (int nt = 0; nt < 8; nt++) {
                #pragma unroll
                for (int r = 0; r < 4; r++) sc[mt][nt][r] *= 0.125f;
                tm0 = fmaxf(tm0, fmaxf(sc[mt][nt][0], sc[mt][nt][1]));
                tm1 = fmaxf(tm1, fmaxf(sc[mt][nt][2], sc[mt][nt][3]));
            }
            tm0 = fmaxf(tm0, __shfl_xor_sync(0xffffffffu, tm0, 1));
            tm0 = fmaxf(tm0, __shfl_xor_sync(0xffffffffu, tm0, 2));
            tm1 = fmaxf(tm1, __shfl_xor_sync(0xffffffffu, tm1, 1));
            tm1 = fmaxf(tm1, __shfl_xor_sync(0xffffffffu, tm1, 2));
            const float mn0 = fmaxf(mst[mt][0], tm0), mn1 = fmaxf(mst[mt][1], tm1);
            const float a0 = __expf(mst[mt][0] - mn0), a1 = __expf(mst[mt][1] - mn1);
            mst[mt][0] = mn0; mst[mt][1] = mn1;

            float rs0 = 0.f, rs1 = 0.f;
            #pragma unroll
            for (int nt = 0; nt < 8; nt++) {
                sc[mt][nt][0] = __expf(sc[mt][nt][0] - mn0);
                sc[mt][nt][1] = __expf(sc[mt][nt][1] - mn0);
                sc[mt][nt][2] = __expf(sc[mt][nt][2] - mn1);
                sc[mt][nt][3] = __expf(sc[mt][nt][3] - mn1);
                rs0 += sc[mt][nt][0] + sc[mt][nt][1];
                rs1 += sc[mt][nt][2] + sc[mt][nt][3];
            }
            rs0 += __shfl_xor_sync(0xffffffffu, rs0, 1);
            rs0 += __shfl_xor_sync(0xffffffffu, rs0, 2);
            rs1 += __shfl_xor_sync(0xffffffffu, rs1, 1);
            rs1 += __shfl_xor_sync(0xffffffffu, rs1, 2);
            lst[mt][0] = lst[mt][0] * a0 + rs0;
            lst[mt][1] = lst[mt][1] * a1 + rs1;

            #pragma unroll
            for (int nt = 0; nt < 8; nt++) {
                o[mt][nt][0] *= a0; o[mt][nt][1] *= a0;
                o[mt][nt][2] *= a1; o[mt][nt][3] *= a1;
            }

            const int pr = w * 32 + mt * 16;
            #pragma unroll
            for (int nt = 0; nt < 8; nt++) {
                *(__half2*)&Ps[pr + g][nt * 8 + 2 * tg]     = __floats2half2_rn(sc[mt][nt][0], sc[mt][nt][1]);
                *(__half2*)&Ps[pr + g + 8][nt * 8 + 2 * tg] = __floats2half2_rn(sc[mt][nt][2], sc[mt][nt][3]);
            }
        }
        __syncwarp();

        // O += P @ V  (P via ldmatrix, V via ldmatrix.trans; V frags reused across m-tiles)
        #pragma unroll
        for (int c = 0; c < 4; c++) {
            uint32_t pa0[4], pa1[4];
            ldm_x4(pa0, psBase + ((w * 32 + aRow) * PST + c * 16 + aCol) * 2);
            ldm_x4(pa1, psBase + ((w * 32 + 16 + aRow) * PST + c * 16 + aCol) * 2);
            #pragma unroll
            for (int ntp = 0; ntp < 4; ntp++) {
                uint32_t r4[4];
                ldm_x4_trans(r4, vsBase + ((c * 16 + vKey) * KST + ntp * 16 + vCol) * 2);
                uint32_t v0[2] = {r4[0], r4[1]}, v1[2] = {r4[2], r4[3]};
                mma_f16(o[0][ntp * 2],     pa0, v0);
                mma_f16(o[0][ntp * 2 + 1], pa0, v1);
                mma_f16(o[1][ntp * 2],     pa1, v0);
                mma_f16(o[1][ntp * 2 + 1], pa1, v1);
            }
        }
        __syncthreads();
    }

    #pragma unroll
    for (int mt = 0; mt < 2; mt++) {
        const float inv0 = 1.f / lst[mt][0], inv1 = 1.f / lst[mt][1];
        __half* c0p = ctx + (size_t)(qrow0 + mt * 16 + g)     * DIMC + h * HDIM;
        __half* c1p = ctx + (size_t)(qrow0 + mt * 16 + g + 8) * DIMC + h * HDIM;
        #pragma unroll
        for (int nt = 0; nt < 8; nt++) {
            *(__half2*)&c0p[nt * 8 + 2 * tg] =
                __floats2half2_rn(o[mt][nt][0] * inv0, o[mt][nt][1] * inv0);
            *(__half2*)&c1p[nt * 8 + 2 * tg] =
                __floats2half2_rn(o[mt][nt][2] * inv1, o[mt][nt][3] * inv1);
        }
    }
}

// ---------------- launch ----------------
extern "C" void kernel_launch(void* const* d_in, const int* in_sizes, int n_in,
                              void* d_out, int out_size)
{
    const float* x    = (const float*)d_in[0];
    const float* ln1g = (const float*)d_in[1];
    const float* ln1b = (const float*)d_in[2];
    const float* Wq   = (const float*)d_in[3];
    const float* bq   = (const float*)d_in[4];
    const float* Wk   = (const float*)d_in[5];
    const float* bk   = (const float*)d_in[6];
    const float* Wv   = (const float*)d_in[7];
    const float* bv   = (const float*)d_in[8];
    const float* Wo   = (const float*)d_in[9];
    const float* bo   = (const float*)d_in[10];
    const float* ln2g = (const float*)d_in[11];
    const float* ln2b = (const float*)d_in[12];
    const float* W1   = (const float*)d_in[13];
    const float* b1   = (const float*)d_in[14];
    const float* W2   = (const float*)d_in[15];
    const float* b2   = (const float*)d_in[16];
    float* out = (float*)d_out;

    __half *h, *qkv, *ctx, *h2, *ffn, *wqkv, *wo, *w1, *w2;
    float *x1, *bqkv;
    cudaGetSymbolAddress((void**)&h,    g_h);
    cudaGetSymbolAddress((void**)&qkv,  g_qkv);
    cudaGetSymbolAddress((void**)&ctx,  g_ctx);
    cudaGetSymbolAddress((void**)&x1,   g_x1);
    cudaGetSymbolAddress((void**)&h2,   g_h2);
    cudaGetSymbolAddress((void**)&ffn,  g_ffn);
    cudaGetSymbolAddress((void**)&wqkv, g_wqkv);
    cudaGetSymbolAddress((void**)&bqkv, g_bqkv);
    cudaGetSymbolAddress((void**)&wo,   g_wo);
    cudaGetSymbolAddress((void**)&w1,   g_w1);
    cudaGetSymbolAddress((void**)&w2,   g_w2);

    cudaFuncSetAttribute(gemm_f16<float>,  cudaFuncAttributeMaxDynamicSharedMemorySize, GEMM_SMEM);
    cudaFuncSetAttribute(gemm_f16<__half>, cudaFuncAttributeMaxDynamicSharedMemorySize, GEMM_SMEM);

    const dim3 blk(256);
    const dim3 gblk(128);

    transpose_f16<<<dim3(DIMC/32, DIMC/32), 256>>>(Wq, wqkv,                   DIMC, DIMC);
    transpose_f16<<<dim3(DIMC/32, DIMC/32), 256>>>(Wk, wqkv + DIMC*DIMC,       DIMC, DIMC);
    transpose_f16<<<dim3(DIMC/32, DIMC/32), 256>>>(Wv, wqkv + 2*DIMC*DIMC,     DIMC, DIMC);
    pack_qkv_b<<<(QKVN + 255) / 256, blk>>>(bq, bk, bv, bqkv);
    transpose_f16<<<dim3(DIMC/32, DIMC/32),    256>>>(Wo, wo, DIMC, DIMC);
    transpose_f16<<<dim3(DIMC/32, HIDDENC/32), 256>>>(W1, w1, DIMC, HIDDENC);
    transpose_f16<<<dim3(HIDDENC/32, DIMC/32), 256>>>(W2, w2, HIDDENC, DIMC);

    const dim3 gqkv(QKVN / 128, NTOK / 128);
    const dim3 gd(DIMC / 128, NTOK / 128);
    const dim3 gh(HIDDENC / 128, NTOK / 128);

    // 1) LN1 -> fp16
    ln_kernel<<<NTOK, blk>>>(x, ln1g, ln1b, h);
    // 2) fused QKV projection -> fp16 qkv
    gemm_f16<__half><<<gqkv, gblk, GEMM_SMEM>>>(h, wqkv, bqkv, nullptr, qkv, NTOK, QKVN, DIMC, 0);
    // 3) fp16 flash attention -> fp16 ctx
    attn_f16<<<dim3(SEQ / 128, HEADSC, BATCH), 128>>>(qkv, ctx);
    // 4) x1 = x + ctx@Wo + bo (fp32 out)
    gemm_f16<float><<<gd, gblk, GEMM_SMEM>>>(ctx, wo, bo, x, x1, NTOK, DIMC, DIMC, 0);
    // 5) LN2 -> fp16
    ln_kernel<<<NTOK, blk>>>(x1, ln2g, ln2b, h2);
    // 6) FFN up + exact GELU -> fp16
    gemm_f16<__half><<<gh, gblk, GEMM_SMEM>>>(h2, w1, b1, nullptr, ffn, NTOK, HIDDENC, DIMC, 1);
    // 7) out = x1 + ffn@W2 + b2 (fp32 out)
    gemm_f16<float><<<gd, gblk, GEMM_SMEM>>>(ffn, w2, b2, x1, out, NTOK, DIMC, HIDDENC, 0);
}